// round 2
// baseline (speedup 1.0000x reference)
#include <cuda_runtime.h>
#include <math.h>

#define SEQ 4096
#define CH  2048
#define NH  16
#define HD  128
#define EPSF 1.1920929e-07f

// Scratch (allocation-free): q, k, v, attn-out, each [SEQ, CH] fp32 (32 MB each)
__device__ float g_q[SEQ * CH];
__device__ float g_k[SEQ * CH];
__device__ float g_v[SEQ * CH];
__device__ float g_attn[SEQ * CH];

// ---------------------------------------------------------------------------
// SGEMM: Out[m,n] = sum_k A[m,k] * B[n,k] + bias[n]
// A: [M,K] row-major, B: [N,K] row-major (i.e. computes A @ B^T + bias)
// BM=BN=128, BK=16, 256 threads, 8x8 per-thread tile.
// ---------------------------------------------------------------------------
__global__ void __launch_bounds__(256, 2) sgemm_abT(
    const float* __restrict__ A, const float* __restrict__ B,
    const float* __restrict__ bias, float* __restrict__ Out,
    int M, int N, int K)
{
    const int BM = 128, BN = 128, BK = 16, TM = 8, TN = 8;
    __shared__ float As[BK][BM];
    __shared__ float Bs[BK][BN];

    const int bm = blockIdx.y * BM;
    const int bn = blockIdx.x * BN;
    const int tid = threadIdx.x;
    const int tx = tid & 15;      // 0..15 -> N direction
    const int ty = tid >> 4;      // 0..15 -> M direction

    float acc[TM][TN];
#pragma unroll
    for (int i = 0; i < TM; i++)
#pragma unroll
        for (int j = 0; j < TN; j++) acc[i][j] = 0.f;

    const int lr = tid >> 2;          // 0..63
    const int lc = (tid & 3) * 4;     // 0,4,8,12

    for (int k0 = 0; k0 < K; k0 += BK) {
        // Load A tile 128x16 (transposed into As[k][m])
#pragma unroll
        for (int i = 0; i < 2; i++) {
            int r = lr + i * 64;
            float4 v = *(const float4*)(A + (size_t)(bm + r) * K + k0 + lc);
            As[lc + 0][r] = v.x; As[lc + 1][r] = v.y;
            As[lc + 2][r] = v.z; As[lc + 3][r] = v.w;
        }
        // Load B tile 128x16 (transposed into Bs[k][n])
#pragma unroll
        for (int i = 0; i < 2; i++) {
            int r = lr + i * 64;
            float4 v = *(const float4*)(B + (size_t)(bn + r) * K + k0 + lc);
            Bs[lc + 0][r] = v.x; Bs[lc + 1][r] = v.y;
            Bs[lc + 2][r] = v.z; Bs[lc + 3][r] = v.w;
        }
        __syncthreads();

#pragma unroll
        for (int kk = 0; kk < BK; kk++) {
            float ar[TM], br[TN];
            *(float4*)(ar + 0) = *(const float4*)&As[kk][ty * TM + 0];
            *(float4*)(ar + 4) = *(const float4*)&As[kk][ty * TM + 4];
            *(float4*)(br + 0) = *(const float4*)&Bs[kk][tx * TN + 0];
            *(float4*)(br + 4) = *(const float4*)&Bs[kk][tx * TN + 4];
#pragma unroll
            for (int i = 0; i < TM; i++)
#pragma unroll
                for (int j = 0; j < TN; j++)
                    acc[i][j] = fmaf(ar[i], br[j], acc[i][j]);
        }
        __syncthreads();
    }

    // Epilogue: add bias, store
#pragma unroll
    for (int i = 0; i < TM; i++) {
        int r = bm + ty * TM + i;
#pragma unroll
        for (int j = 0; j < TN; j += 4) {
            int cn = bn + tx * TN + j;
            float4 o;
            o.x = acc[i][j + 0] + bias[cn + 0];
            o.y = acc[i][j + 1] + bias[cn + 1];
            o.z = acc[i][j + 2] + bias[cn + 2];
            o.w = acc[i][j + 3] + bias[cn + 3];
            *(float4*)(Out + (size_t)r * N + cn) = o;
        }
    }
}

// ---------------------------------------------------------------------------
// Fused RMSNorm (over head_dim) + table-driven rotary, in place on [SEQ,NH,HD].
// One warp per (s,h) row; each lane owns 4 consecutive elements = 2 rope pairs.
// rope flat layout: [s][pair (64)][j (2)][k (2)] -> s*256 + p*4 + j*2 + k
// ---------------------------------------------------------------------------
__global__ void rmsnorm_rope(float* __restrict__ qk, const float* __restrict__ w,
                             const float* __restrict__ rope)
{
    int gwarp = (blockIdx.x * blockDim.x + threadIdx.x) >> 5;
    int lane  = threadIdx.x & 31;
    if (gwarp >= SEQ * NH) return;
    int s = gwarp / NH;

    float* row = qk + (size_t)gwarp * HD;
    float4 v = *(float4*)(row + lane * 4);
    float ss = v.x * v.x + v.y * v.y + v.z * v.z + v.w * v.w;
#pragma unroll
    for (int m = 16; m; m >>= 1) ss += __shfl_xor_sync(0xffffffffu, ss, m);
    float inv = rsqrtf(ss * (1.0f / HD) + EPSF);

    float4 wv = *(const float4*)(w + lane * 4);
    float x0 = v.x * inv * wv.x;
    float x1 = v.y * inv * wv.y;
    float x2 = v.z * inv * wv.z;
    float x3 = v.w * inv * wv.w;

    const float* rp = rope + (size_t)s * 256 + (size_t)(2 * lane) * 4;
    float4 r0 = *(const float4*)rp;        // pair p0: r[0][0],r[0][1],r[1][0],r[1][1]
    float4 r1 = *(const float4*)(rp + 4);  // pair p1

    float o0 = r0.x * x0 + r0.y * x1;
    float o1 = r0.z * x0 + r0.w * x1;
    float o2 = r1.x * x2 + r1.y * x3;
    float o3 = r1.z * x2 + r1.w * x3;
    *(float4*)(row + lane * 4) = make_float4(o0, o1, o2, o3);
}

// ---------------------------------------------------------------------------
// Flash-style fp32 attention. Grid: (SEQ/64, NH). 256 threads.
// Tiles: BR=64 q-rows, BC=64 k-rows, D=128.
// Thread map: tx = tid&15 (key/col dir), ty = tid>>4 (query/row dir).
// Scores: 4x4 per thread; O: rows ty*4+i, cols tx*8+j (4x8 per thread).
// ---------------------------------------------------------------------------
#define BR 64
#define BC 64
#define LDK 132                      // padded row length for Q/K/V tiles
#define FLASH_SMEM ((3 * BC * LDK + BC * (BR + 1)) * 4)

__global__ void __launch_bounds__(256, 1) flash_fp32(
    const float* __restrict__ Q, const float* __restrict__ K,
    const float* __restrict__ V, float* __restrict__ O)
{
    extern __shared__ float sm[];
    float* Qs = sm;                       // [BR][LDK]
    float* Ks = Qs + BR * LDK;            // [BC][LDK]
    float* Vs = Ks + BC * LDK;            // [BC][LDK]
    float* Pt = Vs + BC * LDK;            // [BC][BR+1]  (transposed P)

    const int h  = blockIdx.y;
    const int q0 = blockIdx.x * BR;
    const int tid = threadIdx.x;
    const int tx = tid & 15;
    const int ty = tid >> 4;
    const float scale = 0.088388347648318447f;  // 1/sqrt(128)

    // Load Q tile (coalesced)
    for (int i = tid; i < BR * 32; i += 256) {
        int r = i >> 5, c = (i & 31) * 4;
        *(float4*)&Qs[r * LDK + c] =
            *(const float4*)(Q + (size_t)(q0 + r) * CH + h * HD + c);
    }

    float m[4], l[4], o[4][8];
#pragma unroll
    for (int i = 0; i < 4; i++) {
        m[i] = -INFINITY; l[i] = 0.f;
#pragma unroll
        for (int j = 0; j < 8; j++) o[i][j] = 0.f;
    }

    for (int kt = 0; kt < SEQ; kt += BC) {
        __syncthreads();   // Q ready (iter 0) / prev PV done before overwrite
        for (int i = tid; i < BC * 32; i += 256) {
            int r = i >> 5, c = (i & 31) * 4;
            *(float4*)&Ks[r * LDK + c] =
                *(const float4*)(K + (size_t)(kt + r) * CH + h * HD + c);
            *(float4*)&Vs[r * LDK + c] =
                *(const float4*)(V + (size_t)(kt + r) * CH + h * HD + c);
        }
        __syncthreads();

        // Scores: sc[i][j] = Qs[ty*4+i] . Ks[tx*4+j]
        float sc[4][4];
#pragma unroll
        for (int i = 0; i < 4; i++)
#pragma unroll
            for (int j = 0; j < 4; j++) sc[i][j] = 0.f;

#pragma unroll 4
        for (int d4 = 0; d4 < HD; d4 += 4) {
            float4 q4[4], k4[4];
#pragma unroll
            for (int i = 0; i < 4; i++)
                q4[i] = *(const float4*)&Qs[(ty * 4 + i) * LDK + d4];
#pragma unroll
            for (int j = 0; j < 4; j++)
                k4[j] = *(const float4*)&Ks[(tx * 4 + j) * LDK + d4];
#pragma unroll
            for (int i = 0; i < 4; i++)
#pragma unroll
                for (int j = 0; j < 4; j++) {
                    sc[i][j] = fmaf(q4[i].x, k4[j].x, sc[i][j]);
                    sc[i][j] = fmaf(q4[i].y, k4[j].y, sc[i][j]);
                    sc[i][j] = fmaf(q4[i].z, k4[j].z, sc[i][j]);
                    sc[i][j] = fmaf(q4[i].w, k4[j].w, sc[i][j]);
                }
        }

        // Online softmax per row (rows replicated over the 16 tx lanes)
#pragma unroll
        for (int i = 0; i < 4; i++) {
#pragma unroll
            for (int j = 0; j < 4; j++) sc[i][j] *= scale;
            float rm = fmaxf(fmaxf(sc[i][0], sc[i][1]), fmaxf(sc[i][2], sc[i][3]));
#pragma unroll
            for (int msk = 8; msk; msk >>= 1)
                rm = fmaxf(rm, __shfl_xor_sync(0xffffffffu, rm, msk));
            float mn = fmaxf(m[i], rm);
            float alpha = expf(m[i] - mn);
            float rs = 0.f;
#pragma unroll
            for (int j = 0; j < 4; j++) {
                float p = expf(sc[i][j] - mn);
                sc[i][j] = p;
                rs += p;
            }
#pragma unroll
            for (int msk = 8; msk; msk >>= 1)
                rs += __shfl_xor_sync(0xffffffffu, rs, msk);
            l[i] = l[i] * alpha + rs;
            m[i] = mn;
#pragma unroll
            for (int j = 0; j < 8; j++) o[i][j] *= alpha;
#pragma unroll
            for (int j = 0; j < 4; j++)
                Pt[(tx * 4 + j) * (BR + 1) + ty * 4 + i] = sc[i][j];
        }
        __syncthreads();

        // PV: o[i][j] += sum_c Pt[c][ty*4+i] * Vs[c][tx*8+j]
#pragma unroll 4
        for (int c = 0; c < BC; c++) {
            float pr[4];
#pragma unroll
            for (int i = 0; i < 4; i++) pr[i] = Pt[c * (BR + 1) + ty * 4 + i];
            float4 v0 = *(const float4*)&Vs[c * LDK + tx * 8 + 0];
            float4 v1 = *(const float4*)&Vs[c * LDK + tx * 8 + 4];
#pragma unroll
            for (int i = 0; i < 4; i++) {
                o[i][0] = fmaf(pr[i], v0.x, o[i][0]);
                o[i][1] = fmaf(pr[i], v0.y, o[i][1]);
                o[i][2] = fmaf(pr[i], v0.z, o[i][2]);
                o[i][3] = fmaf(pr[i], v0.w, o[i][3]);
                o[i][4] = fmaf(pr[i], v1.x, o[i][4]);
                o[i][5] = fmaf(pr[i], v1.y, o[i][5]);
                o[i][6] = fmaf(pr[i], v1.z, o[i][6]);
                o[i][7] = fmaf(pr[i], v1.w, o[i][7]);
            }
        }
    }

    // Epilogue: normalize and store
#pragma unroll
    for (int i = 0; i < 4; i++) {
        float invl = 1.f / l[i];
        int r = q0 + ty * 4 + i;
        float4 a, b;
        a.x = o[i][0] * invl; a.y = o[i][1] * invl;
        a.z = o[i][2] * invl; a.w = o[i][3] * invl;
        b.x = o[i][4] * invl; b.y = o[i][5] * invl;
        b.z = o[i][6] * invl; b.w = o[i][7] * invl;
        *(float4*)(O + (size_t)r * CH + h * HD + tx * 8 + 0) = a;
        *(float4*)(O + (size_t)r * CH + h * HD + tx * 8 + 4) = b;
    }
}

// ---------------------------------------------------------------------------
extern "C" void kernel_launch(void* const* d_in, const int* in_sizes, int n_in,
                              void* d_out, int out_size)
{
    (void)in_sizes; (void)n_in; (void)out_size;
    const float* x    = (const float*)d_in[0];
    const float* rope = (const float*)d_in[1];
    const float* Wq   = (const float*)d_in[2];
    const float* bq   = (const float*)d_in[3];
    const float* Wk   = (const float*)d_in[4];
    const float* bk   = (const float*)d_in[5];
    const float* Wv   = (const float*)d_in[6];
    const float* bv   = (const float*)d_in[7];
    const float* qn   = (const float*)d_in[8];
    const float* kn   = (const float*)d_in[9];
    const float* Wo   = (const float*)d_in[10];
    const float* bo   = (const float*)d_in[11];
    float* out = (float*)d_out;

    float *gq, *gk, *gv, *ga;
    cudaGetSymbolAddress((void**)&gq, g_q);
    cudaGetSymbolAddress((void**)&gk, g_k);
    cudaGetSymbolAddress((void**)&gv, g_v);
    cudaGetSymbolAddress((void**)&ga, g_attn);

    dim3 gg(CH / 128, SEQ / 128);
    sgemm_abT<<<gg, 256>>>(x, Wq, bq, gq, SEQ, CH, CH);
    sgemm_abT<<<gg, 256>>>(x, Wk, bk, gk, SEQ, CH, CH);
    sgemm_abT<<<gg, 256>>>(x, Wv, bv, gv, SEQ, CH, CH);

    rmsnorm_rope<<<SEQ * NH / 8, 256>>>(gq, qn, rope);
    rmsnorm_rope<<<SEQ * NH / 8, 256>>>(gk, kn, rope);

    cudaFuncSetAttribute(flash_fp32,
                         cudaFuncAttributeMaxDynamicSharedMemorySize, FLASH_SMEM);
    flash_fp32<<<dim3(SEQ / BR, NH), 256, FLASH_SMEM>>>(gq, gk, gv, ga);

    sgemm_abT<<<gg, 256>>>(ga, Wo, bo, out, SEQ, CH, CH);
}

// round 6
// speedup vs baseline: 1.3624x; 1.3624x over previous
#include <cuda_runtime.h>
#include <cuda_bf16.h>
#include <cstdint>
#include <math.h>

#define SEQ 4096
#define CH  2048
#define NH  16
#define HD  128
#define EPSF 1.1920929e-07f

// Scratch (allocation-free __device__ globals)
__device__ float g_q[SEQ * CH];
__device__ float g_k[SEQ * CH];
__device__ float g_v[SEQ * CH];
__device__ float g_attn[SEQ * CH];     // flash output, already tf32-rounded
__device__ float g_xr[SEQ * CH];       // tf32-rounded x
__device__ float g_wqr[CH * CH];
__device__ float g_wkr[CH * CH];
__device__ float g_wvr[CH * CH];
__device__ float g_wor[CH * CH];

// ===========================================================================
// Helpers
// ===========================================================================
__device__ __forceinline__ uint32_t smem_u32(const void* p) {
    uint32_t a;
    asm("{ .reg .u64 t; cvta.to.shared.u64 t, %1; cvt.u32.u64 %0, t; }"
        : "=r"(a) : "l"(p));
    return a;
}

__device__ __forceinline__ float round_tf32_rna(float x) {
    uint32_t u;
    asm("cvt.rna.tf32.f32 %0, %1;" : "=r"(u) : "f"(x));
    return __uint_as_float(u);
}

#define LDMATRIX_X4(r0, r1, r2, r3, addr)                                     \
    asm volatile("ldmatrix.sync.aligned.m8n8.x4.shared.b16 {%0,%1,%2,%3}, [%4];" \
                 : "=r"(r0), "=r"(r1), "=r"(r2), "=r"(r3) : "r"(addr))

#define MMA_TF32(d, a, b0, b1)                                                \
    asm volatile(                                                             \
        "mma.sync.aligned.m16n8k8.row.col.f32.tf32.tf32.f32 "                 \
        "{%0,%1,%2,%3}, {%4,%5,%6,%7}, {%8,%9}, {%0,%1,%2,%3};"               \
        : "+f"((d)[0]), "+f"((d)[1]), "+f"((d)[2]), "+f"((d)[3])              \
        : "r"((a)[0]), "r"((a)[1]), "r"((a)[2]), "r"((a)[3]),                 \
          "r"(b0), "r"(b1))

// ===========================================================================
// tf32 rounding kernel (elementwise, float4)
// ===========================================================================
__global__ void round_tf32_kernel(const float* __restrict__ in,
                                  float* __restrict__ out, int n4)
{
    int i = blockIdx.x * blockDim.x + threadIdx.x;
    if (i >= n4) return;
    float4 v = ((const float4*)in)[i];
    float4 o;
    o.x = round_tf32_rna(v.x);
    o.y = round_tf32_rna(v.y);
    o.z = round_tf32_rna(v.z);
    o.w = round_tf32_rna(v.w);
    ((float4*)out)[i] = o;
}

// ===========================================================================
// mma.sync tf32 GEMM: Out[m,n] = sum_k A[m,k]*B[n,k] + bias[n]
// CTA 128x128, K-chunk 32 (128B rows, swizzled), 8 warps (2x4), warp 64x32.
// Double-buffered cp.async. tf32 m16n8k8 via ldmatrix b16 trick.
// ===========================================================================
#define GBM 128
#define GBN 128
#define GCK 32
#define GSTAGE_BYTES (GBM * GCK * 4)             // 16 KB per matrix per stage
#define GSMEM_BYTES  (4 * GSTAGE_BYTES)          // 64 KB (2 stages x A,B)

__device__ __forceinline__ void g_load_chunk(
    const float* __restrict__ A, const float* __restrict__ B,
    int bm, int bn, int K, int k0, uint32_t sA, uint32_t sB, int tid)
{
#pragma unroll
    for (int t = 0; t < 4; t++) {
        int s = tid + t * 256;
        int r = s >> 3;
        int cb = (s & 7) * 16;
        uint32_t sw = (uint32_t)(r * 128) + ((uint32_t)cb ^ (((uint32_t)r & 7u) << 4));
        const float* ga = A + (size_t)(bm + r) * K + k0 + (cb >> 2);
        asm volatile("cp.async.cg.shared.global [%0], [%1], 16;"
                     :: "r"(sA + sw), "l"(ga));
    }
#pragma unroll
    for (int t = 0; t < 4; t++) {
        int s = tid + t * 256;
        int r = s >> 3;
        int cb = (s & 7) * 16;
        uint32_t sw = (uint32_t)(r * 128) + ((uint32_t)cb ^ (((uint32_t)r & 7u) << 4));
        const float* gb = B + (size_t)(bn + r) * K + k0 + (cb >> 2);
        asm volatile("cp.async.cg.shared.global [%0], [%1], 16;"
                     :: "r"(sB + sw), "l"(gb));
    }
    asm volatile("cp.async.commit_group;" ::: "memory");
}

__global__ void __launch_bounds__(256, 2)
gemm_mma_tf32(const float* __restrict__ A, const float* __restrict__ B,
              const float* __restrict__ bias, float* __restrict__ Out,
              int M, int N, int K)
{
    extern __shared__ char smem[];
    const uint32_t sb = smem_u32(smem);
    const int tid  = threadIdx.x;
    const int wid  = tid >> 5;
    const int lane = tid & 31;
    const int bm = blockIdx.y * GBM;
    const int bn = blockIdx.x * GBN;
    const int wm = wid >> 2;            // 0..1 -> M
    const int wn = wid & 3;             // 0..3 -> N
    const int NCHUNK = K / GCK;

    const uint32_t bufA0 = sb;
    const uint32_t bufB0 = sb + GSTAGE_BYTES;
    const uint32_t bufA1 = sb + 2 * GSTAGE_BYTES;
    const uint32_t bufB1 = sb + 3 * GSTAGE_BYTES;

    // Per-thread ldmatrix address components.
    // A (m16 tile): lanes 0-7 mat0 (rows+0, +0B), 8-15 mat1 (rows+8, +0B),
    //               16-23 mat2 (rows+0, +16B), 24-31 mat3 (rows+8, +16B)
    const int a_row = wm * 64 + (lane & 7) + ((lane >> 3) & 1) * 8;
    const int a_cb  = ((lane >> 4) & 1) * 16;
    // B (n8-pair): lanes 0-7 mat0 (rows+0, +0B), 8-15 mat1 (rows+0, +16B),
    //              16-23 mat2 (rows+8, +0B), 24-31 mat3 (rows+8, +16B)
    const int b_row = wn * 32 + (lane & 7) + ((lane >> 4) & 1) * 8;
    const int b_cb  = ((lane >> 3) & 1) * 16;

    float d[4][4][4];
#pragma unroll
    for (int mi = 0; mi < 4; mi++)
#pragma unroll
        for (int ni = 0; ni < 4; ni++)
#pragma unroll
            for (int r = 0; r < 4; r++) d[mi][ni][r] = 0.f;

    g_load_chunk(A, B, bm, bn, K, 0,   bufA0, bufB0, tid);
    g_load_chunk(A, B, bm, bn, K, GCK, bufA1, bufB1, tid);

    for (int i = 0; i < NCHUNK; i++) {
        const int b = i & 1;
        if (i >= NCHUNK - 2) asm volatile("cp.async.wait_group 0;" ::: "memory");
        else                 asm volatile("cp.async.wait_group 1;" ::: "memory");
        __syncthreads();

        const uint32_t As = b ? bufA1 : bufA0;
        const uint32_t Bs = b ? bufB1 : bufB0;

#pragma unroll
        for (int ks = 0; ks < 4; ks++) {
            uint32_t af[4][4], bf[2][4];
#pragma unroll
            for (int mi = 0; mi < 4; mi++) {
                int row = a_row + mi * 16;
                uint32_t cb = (uint32_t)(ks * 32 + a_cb) ^ (((uint32_t)row & 7u) << 4);
                LDMATRIX_X4(af[mi][0], af[mi][1], af[mi][2], af[mi][3],
                            As + (uint32_t)row * 128 + cb);
            }
#pragma unroll
            for (int p = 0; p < 2; p++) {
                int row = b_row + p * 16;
                uint32_t cb = (uint32_t)(ks * 32 + b_cb) ^ (((uint32_t)row & 7u) << 4);
                LDMATRIX_X4(bf[p][0], bf[p][1], bf[p][2], bf[p][3],
                            Bs + (uint32_t)row * 128 + cb);
            }
#pragma unroll
            for (int mi = 0; mi < 4; mi++) {
#pragma unroll
                for (int ni = 0; ni < 4; ni++) {
                    MMA_TF32(d[mi][ni], af[mi],
                             bf[ni >> 1][(ni & 1) * 2 + 0],
                             bf[ni >> 1][(ni & 1) * 2 + 1]);
                }
            }
        }
        __syncthreads();

        if (i + 2 < NCHUNK)
            g_load_chunk(A, B, bm, bn, K, (i + 2) * GCK,
                         b ? bufA1 : bufA0, b ? bufB1 : bufB0, tid);
    }

    // Epilogue: direct float2 stores (+bias)
    const int gid = lane >> 2, tig = lane & 3;
#pragma unroll
    for (int mi = 0; mi < 4; mi++) {
#pragma unroll
        for (int ni = 0; ni < 4; ni++) {
            int r0 = bm + wm * 64 + mi * 16 + gid;
            int c  = bn + wn * 32 + ni * 8 + tig * 2;
            float bx = bias[c], by = bias[c + 1];
            float2 v0 = make_float2(d[mi][ni][0] + bx, d[mi][ni][1] + by);
            float2 v1 = make_float2(d[mi][ni][2] + bx, d[mi][ni][3] + by);
            *(float2*)(Out + (size_t)r0 * N + c) = v0;
            *(float2*)(Out + (size_t)(r0 + 8) * N + c) = v1;
        }
    }
}

// ===========================================================================
// Fused RMSNorm + rotary (unchanged)
// ===========================================================================
__global__ void rmsnorm_rope(float* __restrict__ qk, const float* __restrict__ w,
                             const float* __restrict__ rope)
{
    int gwarp = (blockIdx.x * blockDim.x + threadIdx.x) >> 5;
    int lane  = threadIdx.x & 31;
    if (gwarp >= SEQ * NH) return;
    int s = gwarp / NH;

    float* row = qk + (size_t)gwarp * HD;
    float4 v = *(float4*)(row + lane * 4);
    float ss = v.x * v.x + v.y * v.y + v.z * v.z + v.w * v.w;
#pragma unroll
    for (int m = 16; m; m >>= 1) ss += __shfl_xor_sync(0xffffffffu, ss, m);
    float inv = rsqrtf(ss * (1.0f / HD) + EPSF);

    float4 wv = *(const float4*)(w + lane * 4);
    float x0 = v.x * inv * wv.x;
    float x1 = v.y * inv * wv.y;
    float x2 = v.z * inv * wv.z;
    float x3 = v.w * inv * wv.w;

    const float* rp = rope + (size_t)s * 256 + (size_t)(2 * lane) * 4;
    float4 r0 = *(const float4*)rp;
    float4 r1 = *(const float4*)(rp + 4);

    float o0 = r0.x * x0 + r0.y * x1;
    float o1 = r0.z * x0 + r0.w * x1;
    float o2 = r1.x * x2 + r1.y * x3;
    float o3 = r1.z * x2 + r1.w * x3;
    *(float4*)(row + lane * 4) = make_float4(o0, o1, o2, o3);
}

// ===========================================================================
// Flash-style fp32 attention (output tf32-RNA rounded for the final GEMM)
// ===========================================================================
#define BR 64
#define BC 64
#define LDK 132
#define FLASH_SMEM ((3 * BC * LDK + BC * (BR + 1)) * 4)

__global__ void __launch_bounds__(256, 1) flash_fp32(
    const float* __restrict__ Q, const float* __restrict__ K,
    const float* __restrict__ V, float* __restrict__ O)
{
    extern __shared__ float sm[];
    float* Qs = sm;
    float* Ks = Qs + BR * LDK;
    float* Vs = Ks + BC * LDK;
    float* Pt = Vs + BC * LDK;

    const int h  = blockIdx.y;
    const int q0 = blockIdx.x * BR;
    const int tid = threadIdx.x;
    const int tx = tid & 15;
    const int ty = tid >> 4;
    const float scale = 0.088388347648318447f;

    for (int i = tid; i < BR * 32; i += 256) {
        int r = i >> 5, c = (i & 31) * 4;
        *(float4*)&Qs[r * LDK + c] =
            *(const float4*)(Q + (size_t)(q0 + r) * CH + h * HD + c);
    }

    float m[4], l[4], o[4][8];
#pragma unroll
    for (int i = 0; i < 4; i++) {
        m[i] = -INFINITY; l[i] = 0.f;
#pragma unroll
        for (int j = 0; j < 8; j++) o[i][j] = 0.f;
    }

    for (int kt = 0; kt < SEQ; kt += BC) {
        __syncthreads();
        for (int i = tid; i < BC * 32; i += 256) {
            int r = i >> 5, c = (i & 31) * 4;
            *(float4*)&Ks[r * LDK + c] =
                *(const float4*)(K + (size_t)(kt + r) * CH + h * HD + c);
            *(float4*)&Vs[r * LDK + c] =
                *(const float4*)(V + (size_t)(kt + r) * CH + h * HD + c);
        }
        __syncthreads();

        float sc[4][4];
#pragma unroll
        for (int i = 0; i < 4; i++)
#pragma unroll
            for (int j = 0; j < 4; j++) sc[i][j] = 0.f;

#pragma unroll 4
        for (int d4 = 0; d4 < HD; d4 += 4) {
            float4 q4[4], k4[4];
#pragma unroll
            for (int i = 0; i < 4; i++)
                q4[i] = *(const float4*)&Qs[(ty * 4 + i) * LDK + d4];
#pragma unroll
            for (int j = 0; j < 4; j++)
                k4[j] = *(const float4*)&Ks[(tx * 4 + j) * LDK + d4];
#pragma unroll
            for (int i = 0; i < 4; i++)
#pragma unroll
                for (int j = 0; j < 4; j++) {
                    sc[i][j] = fmaf(q4[i].x, k4[j].x, sc[i][j]);
                    sc[i][j] = fmaf(q4[i].y, k4[j].y, sc[i][j]);
                    sc[i][j] = fmaf(q4[i].z, k4[j].z, sc[i][j]);
                    sc[i][j] = fmaf(q4[i].w, k4[j].w, sc[i][j]);
                }
        }

#pragma unroll
        for (int i = 0; i < 4; i++) {
#pragma unroll
            for (int j = 0; j < 4; j++) sc[i][j] *= scale;
            float rm = fmaxf(fmaxf(sc[i][0], sc[i][1]), fmaxf(sc[i][2], sc[i][3]));
#pragma unroll
            for (int msk = 8; msk; msk >>= 1)
                rm = fmaxf(rm, __shfl_xor_sync(0xffffffffu, rm, msk));
            float mn = fmaxf(m[i], rm);
            float alpha = expf(m[i] - mn);
            float rs = 0.f;
#pragma unroll
            for (int j = 0; j < 4; j++) {
                float p = expf(sc[i][j] - mn);
                sc[i][j] = p;
                rs += p;
            }
#pragma unroll
            for (int msk = 8; msk; msk >>= 1)
                rs += __shfl_xor_sync(0xffffffffu, rs, msk);
            l[i] = l[i] * alpha + rs;
            m[i] = mn;
#pragma unroll
            for (int j = 0; j < 8; j++) o[i][j] *= alpha;
#pragma unroll
            for (int j = 0; j < 4; j++)
                Pt[(tx * 4 + j) * (BR + 1) + ty * 4 + i] = sc[i][j];
        }
        __syncthreads();

#pragma unroll 4
        for (int c = 0; c < BC; c++) {
            float pr[4];
#pragma unroll
            for (int i = 0; i < 4; i++) pr[i] = Pt[c * (BR + 1) + ty * 4 + i];
            float4 v0 = *(const float4*)&Vs[c * LDK + tx * 8 + 0];
            float4 v1 = *(const float4*)&Vs[c * LDK + tx * 8 + 4];
#pragma unroll
            for (int i = 0; i < 4; i++) {
                o[i][0] = fmaf(pr[i], v0.x, o[i][0]);
                o[i][1] = fmaf(pr[i], v0.y, o[i][1]);
                o[i][2] = fmaf(pr[i], v0.z, o[i][2]);
                o[i][3] = fmaf(pr[i], v0.w, o[i][3]);
                o[i][4] = fmaf(pr[i], v1.x, o[i][4]);
                o[i][5] = fmaf(pr[i], v1.y, o[i][5]);
                o[i][6] = fmaf(pr[i], v1.z, o[i][6]);
                o[i][7] = fmaf(pr[i], v1.w, o[i][7]);
            }
        }
    }

#pragma unroll
    for (int i = 0; i < 4; i++) {
        float invl = 1.f / l[i];
        int r = q0 + ty * 4 + i;
        float4 a, b;
        a.x = round_tf32_rna(o[i][0] * invl);
        a.y = round_tf32_rna(o[i][1] * invl);
        a.z = round_tf32_rna(o[i][2] * invl);
        a.w = round_tf32_rna(o[i][3] * invl);
        b.x = round_tf32_rna(o[i][4] * invl);
        b.y = round_tf32_rna(o[i][5] * invl);
        b.z = round_tf32_rna(o[i][6] * invl);
        b.w = round_tf32_rna(o[i][7] * invl);
        *(float4*)(O + (size_t)r * CH + h * HD + tx * 8 + 0) = a;
        *(float4*)(O + (size_t)r * CH + h * HD + tx * 8 + 4) = b;
    }
}

// ===========================================================================
extern "C" void kernel_launch(void* const* d_in, const int* in_sizes, int n_in,
                              void* d_out, int out_size)
{
    (void)in_sizes; (void)n_in; (void)out_size;
    const float* x    = (const float*)d_in[0];
    const float* rope = (const float*)d_in[1];
    const float* Wq   = (const float*)d_in[2];
    const float* bq   = (const float*)d_in[3];
    const float* Wk   = (const float*)d_in[4];
    const float* bk   = (const float*)d_in[5];
    const float* Wv   = (const float*)d_in[6];
    const float* bv   = (const float*)d_in[7];
    const float* qn   = (const float*)d_in[8];
    const float* kn   = (const float*)d_in[9];
    const float* Wo   = (const float*)d_in[10];
    const float* bo   = (const float*)d_in[11];
    float* out = (float*)d_out;

    float *gq, *gk, *gv, *ga, *gxr, *gwq, *gwk, *gwv, *gwo;
    cudaGetSymbolAddress((void**)&gq,  g_q);
    cudaGetSymbolAddress((void**)&gk,  g_k);
    cudaGetSymbolAddress((void**)&gv,  g_v);
    cudaGetSymbolAddress((void**)&ga,  g_attn);
    cudaGetSymbolAddress((void**)&gxr, g_xr);
    cudaGetSymbolAddress((void**)&gwq, g_wqr);
    cudaGetSymbolAddress((void**)&gwk, g_wkr);
    cudaGetSymbolAddress((void**)&gwv, g_wvr);
    cudaGetSymbolAddress((void**)&gwo, g_wor);

    cudaFuncSetAttribute(gemm_mma_tf32,
        cudaFuncAttributeMaxDynamicSharedMemorySize, GSMEM_BYTES);
    cudaFuncSetAttribute(flash_fp32,
        cudaFuncAttributeMaxDynamicSharedMemorySize, FLASH_SMEM);

    // Pre-round GEMM inputs to tf32 (RNA)
    const int n4x = SEQ * CH / 4, n4w = CH * CH / 4;
    round_tf32_kernel<<<(n4x + 255) / 256, 256>>>(x,  gxr, n4x);
    round_tf32_kernel<<<(n4w + 255) / 256, 256>>>(Wq, gwq, n4w);
    round_tf32_kernel<<<(n4w + 255) / 256, 256>>>(Wk, gwk, n4w);
    round_tf32_kernel<<<(n4w + 255) / 256, 256>>>(Wv, gwv, n4w);
    round_tf32_kernel<<<(n4w + 255) / 256, 256>>>(Wo, gwo, n4w);

    dim3 gg(CH / GBN, SEQ / GBM);
    gemm_mma_tf32<<<gg, 256, GSMEM_BYTES>>>(gxr, gwq, bq, gq, SEQ, CH, CH);
    gemm_mma_tf32<<<gg, 256, GSMEM_BYTES>>>(gxr, gwk, bk, gk, SEQ, CH, CH);
    gemm_mma_tf32<<<gg, 256, GSMEM_BYTES>>>(gxr, gwv, bv, gv, SEQ, CH, CH);

    rmsnorm_rope<<<SEQ * NH / 8, 256>>>(gq, qn, rope);
    rmsnorm_rope<<<SEQ * NH / 8, 256>>>(gk, kn, rope);

    flash_fp32<<<dim3(SEQ / BR, NH), 256, FLASH_SMEM>>>(gq, gk, gv, ga);

    gemm_mma_tf32<<<gg, 256, GSMEM_BYTES>>>(ga, gwo, bo, out, SEQ, CH, CH);
}

// round 9
// speedup vs baseline: 2.9093x; 2.1354x over previous
#include <cuda_runtime.h>
#include <cuda_bf16.h>
#include <cstdint>
#include <math.h>

#define SEQ 4096
#define CH  2048
#define NH  16
#define HD  128
#define EPSF 1.1920929e-07f

// Scratch (allocation-free __device__ globals)
__device__ float g_q[SEQ * CH];
__device__ float g_k[SEQ * CH];
__device__ float g_v[SEQ * CH];
__device__ float g_vt[CH * SEQ];       // V transposed: [2048 hd][4096 s]
__device__ float g_attn[SEQ * CH];     // flash output, tf32-rounded
__device__ float g_xr[SEQ * CH];       // tf32-rounded x
__device__ float g_wqr[CH * CH];
__device__ float g_wkr[CH * CH];
__device__ float g_wvr[CH * CH];
__device__ float g_wor[CH * CH];

// ===========================================================================
// Helpers
// ===========================================================================
__device__ __forceinline__ uint32_t smem_u32(const void* p) {
    uint32_t a;
    asm("{ .reg .u64 t; cvta.to.shared.u64 t, %1; cvt.u32.u64 %0, t; }"
        : "=r"(a) : "l"(p));
    return a;
}

__device__ __forceinline__ float round_tf32_rna(float x) {
    uint32_t u;
    asm("cvt.rna.tf32.f32 %0, %1;" : "=r"(u) : "f"(x));
    return __uint_as_float(u);
}

#define LDMATRIX_X4(r0, r1, r2, r3, addr)                                     \
    asm volatile("ldmatrix.sync.aligned.m8n8.x4.shared.b16 {%0,%1,%2,%3}, [%4];" \
                 : "=r"(r0), "=r"(r1), "=r"(r2), "=r"(r3) : "r"(addr))

#define MMA_TF32(d, a, b0, b1)                                                \
    asm volatile(                                                             \
        "mma.sync.aligned.m16n8k8.row.col.f32.tf32.tf32.f32 "                 \
        "{%0,%1,%2,%3}, {%4,%5,%6,%7}, {%8,%9}, {%0,%1,%2,%3};"               \
        : "+f"((d)[0]), "+f"((d)[1]), "+f"((d)[2]), "+f"((d)[3])              \
        : "r"((a)[0]), "r"((a)[1]), "r"((a)[2]), "r"((a)[3]),                 \
          "r"(b0), "r"(b1))

#define CP_ASYNC16(dst, src)                                                  \
    asm volatile("cp.async.cg.shared.global [%0], [%1], 16;"                  \
                 :: "r"(dst), "l"(src))
#define CP_COMMIT() asm volatile("cp.async.commit_group;" ::: "memory")
#define CP_WAIT0()  asm volatile("cp.async.wait_group 0;" ::: "memory")

// ===========================================================================
// tf32 rounding kernel (elementwise, float4)
// ===========================================================================
__global__ void round_tf32_kernel(const float* __restrict__ in,
                                  float* __restrict__ out, int n4)
{
    int i = blockIdx.x * blockDim.x + threadIdx.x;
    if (i >= n4) return;
    float4 v = ((const float4*)in)[i];
    float4 o;
    o.x = round_tf32_rna(v.x);
    o.y = round_tf32_rna(v.y);
    o.z = round_tf32_rna(v.z);
    o.w = round_tf32_rna(v.w);
    ((float4*)out)[i] = o;
}

// ===========================================================================
// Transpose [4096][2048] -> [2048][4096]  (for V)
// ===========================================================================
__global__ void transpose_kernel(const float* __restrict__ in,
                                 float* __restrict__ out)
{
    __shared__ float t[32][33];
    int bx = blockIdx.x * 32;           // col in input (hd dim)
    int by = blockIdx.y * 32;           // row in input (s dim)
    int x = threadIdx.x, y = threadIdx.y;
#pragma unroll
    for (int i = 0; i < 32; i += 8)
        t[y + i][x] = in[(size_t)(by + y + i) * CH + bx + x];
    __syncthreads();
#pragma unroll
    for (int i = 0; i < 32; i += 8)
        out[(size_t)(bx + y + i) * SEQ + by + x] = t[x][y + i];
}

// ===========================================================================
// mma.sync tf32 GEMM (unchanged from R5): Out = A @ B^T + bias
// ===========================================================================
#define GBM 128
#define GBN 128
#define GCK 32
#define GSTAGE_BYTES (GBM * GCK * 4)
#define GSMEM_BYTES  (4 * GSTAGE_BYTES)

__device__ __forceinline__ void g_load_chunk(
    const float* __restrict__ A, const float* __restrict__ B,
    int bm, int bn, int K, int k0, uint32_t sA, uint32_t sB, int tid)
{
#pragma unroll
    for (int t = 0; t < 4; t++) {
        int s = tid + t * 256;
        int r = s >> 3;
        int cb = (s & 7) * 16;
        uint32_t sw = (uint32_t)(r * 128) + ((uint32_t)cb ^ (((uint32_t)r & 7u) << 4));
        const float* ga = A + (size_t)(bm + r) * K + k0 + (cb >> 2);
        CP_ASYNC16(sA + sw, ga);
    }
#pragma unroll
    for (int t = 0; t < 4; t++) {
        int s = tid + t * 256;
        int r = s >> 3;
        int cb = (s & 7) * 16;
        uint32_t sw = (uint32_t)(r * 128) + ((uint32_t)cb ^ (((uint32_t)r & 7u) << 4));
        const float* gb = B + (size_t)(bn + r) * K + k0 + (cb >> 2);
        CP_ASYNC16(sB + sw, gb);
    }
    CP_COMMIT();
}

__global__ void __launch_bounds__(256, 2)
gemm_mma_tf32(const float* __restrict__ A, const float* __restrict__ B,
              const float* __restrict__ bias, float* __restrict__ Out,
              int M, int N, int K)
{
    extern __shared__ char smem[];
    const uint32_t sb = smem_u32(smem);
    const int tid  = threadIdx.x;
    const int wid  = tid >> 5;
    const int lane = tid & 31;
    const int bm = blockIdx.y * GBM;
    const int bn = blockIdx.x * GBN;
    const int wm = wid >> 2;
    const int wn = wid & 3;
    const int NCHUNK = K / GCK;

    const uint32_t bufA0 = sb;
    const uint32_t bufB0 = sb + GSTAGE_BYTES;
    const uint32_t bufA1 = sb + 2 * GSTAGE_BYTES;
    const uint32_t bufB1 = sb + 3 * GSTAGE_BYTES;

    const int a_row = wm * 64 + (lane & 7) + ((lane >> 3) & 1) * 8;
    const int a_cb  = ((lane >> 4) & 1) * 16;
    const int b_row = wn * 32 + (lane & 7) + ((lane >> 4) & 1) * 8;
    const int b_cb  = ((lane >> 3) & 1) * 16;

    float d[4][4][4];
#pragma unroll
    for (int mi = 0; mi < 4; mi++)
#pragma unroll
        for (int ni = 0; ni < 4; ni++)
#pragma unroll
            for (int r = 0; r < 4; r++) d[mi][ni][r] = 0.f;

    g_load_chunk(A, B, bm, bn, K, 0,   bufA0, bufB0, tid);
    g_load_chunk(A, B, bm, bn, K, GCK, bufA1, bufB1, tid);

    for (int i = 0; i < NCHUNK; i++) {
        const int b = i & 1;
        if (i >= NCHUNK - 2) asm volatile("cp.async.wait_group 0;" ::: "memory");
        else                 asm volatile("cp.async.wait_group 1;" ::: "memory");
        __syncthreads();

        const uint32_t As = b ? bufA1 : bufA0;
        const uint32_t Bs = b ? bufB1 : bufB0;

#pragma unroll
        for (int ks = 0; ks < 4; ks++) {
            uint32_t af[4][4], bf[2][4];
#pragma unroll
            for (int mi = 0; mi < 4; mi++) {
                int row = a_row + mi * 16;
                uint32_t cb = (uint32_t)(ks * 32 + a_cb) ^ (((uint32_t)row & 7u) << 4);
                LDMATRIX_X4(af[mi][0], af[mi][1], af[mi][2], af[mi][3],
                            As + (uint32_t)row * 128 + cb);
            }
#pragma unroll
            for (int p = 0; p < 2; p++) {
                int row = b_row + p * 16;
                uint32_t cb = (uint32_t)(ks * 32 + b_cb) ^ (((uint32_t)row & 7u) << 4);
                LDMATRIX_X4(bf[p][0], bf[p][1], bf[p][2], bf[p][3],
                            Bs + (uint32_t)row * 128 + cb);
            }
#pragma unroll
            for (int mi = 0; mi < 4; mi++) {
#pragma unroll
                for (int ni = 0; ni < 4; ni++) {
                    MMA_TF32(d[mi][ni], af[mi],
                             bf[ni >> 1][(ni & 1) * 2 + 0],
                             bf[ni >> 1][(ni & 1) * 2 + 1]);
                }
            }
        }
        __syncthreads();

        if (i + 2 < NCHUNK)
            g_load_chunk(A, B, bm, bn, K, (i + 2) * GCK,
                         b ? bufA1 : bufA0, b ? bufB1 : bufB0, tid);
    }

    const int gid = lane >> 2, tig = lane & 3;
#pragma unroll
    for (int mi = 0; mi < 4; mi++) {
#pragma unroll
        for (int ni = 0; ni < 4; ni++) {
            int r0 = bm + wm * 64 + mi * 16 + gid;
            int c  = bn + wn * 32 + ni * 8 + tig * 2;
            float bx = bias[c], by = bias[c + 1];
            float2 v0 = make_float2(d[mi][ni][0] + bx, d[mi][ni][1] + by);
            float2 v1 = make_float2(d[mi][ni][2] + bx, d[mi][ni][3] + by);
            *(float2*)(Out + (size_t)r0 * N + c) = v0;
            *(float2*)(Out + (size_t)(r0 + 8) * N + c) = v1;
        }
    }
}

// ===========================================================================
// Fused RMSNorm + rotary (unchanged)
// ===========================================================================
__global__ void rmsnorm_rope(float* __restrict__ qk, const float* __restrict__ w,
                             const float* __restrict__ rope)
{
    int gwarp = (blockIdx.x * blockDim.x + threadIdx.x) >> 5;
    int lane  = threadIdx.x & 31;
    if (gwarp >= SEQ * NH) return;
    int s = gwarp / NH;

    float* row = qk + (size_t)gwarp * HD;
    float4 v = *(float4*)(row + lane * 4);
    float ss = v.x * v.x + v.y * v.y + v.z * v.z + v.w * v.w;
#pragma unroll
    for (int m = 16; m; m >>= 1) ss += __shfl_xor_sync(0xffffffffu, ss, m);
    float inv = rsqrtf(ss * (1.0f / HD) + EPSF);

    float4 wv = *(const float4*)(w + lane * 4);
    float x0 = v.x * inv * wv.x;
    float x1 = v.y * inv * wv.y;
    float x2 = v.z * inv * wv.z;
    float x3 = v.w * inv * wv.w;

    const float* rp = rope + (size_t)s * 256 + (size_t)(2 * lane) * 4;
    float4 r0 = *(const float4*)rp;
    float4 r1 = *(const float4*)(rp + 4);

    float o0 = r0.x * x0 + r0.y * x1;
    float o1 = r0.z * x0 + r0.w * x1;
    float o2 = r1.x * x2 + r1.y * x3;
    float o3 = r1.z * x2 + r1.w * x3;
    *(float4*)(row + lane * 4) = make_float4(o0, o1, o2, o3);
}

// ===========================================================================
// Flash attention via split-tf32 mma.sync.
// BR=BC=64, HD=128. 128 threads = 4 warps; warp w owns q-rows [w*16, w*16+16).
// smem (float offsets):
//   Qs   [4 chunks][64][32]  fp32       @ 0
//   Khi  [4][64][32]                    @ 8192
//   Klo  [4][64][32]                    @ 16384
//   Vthi [2][128][32]                   @ 24576
//   Vtlo [2][128][32]                   @ 32768
//   Ps   [2][64][32]  fp32             @ 40960
// All chunk rows are 128B with XOR swizzle ((row&7)<<4) on the 16B column.
// ===========================================================================
#define BRF 64
#define BCF 64
#define F_SMEM_BYTES (45056 * 4)

__device__ __forceinline__ void f_load_kv(
    const float* __restrict__ K, const float* __restrict__ Vt,
    int h, int kt, uint32_t sKh, uint32_t sVh, int tid)
{
    // K tile: 64 rows (keys) x 128 floats -> 4 chunks [64][32]
#pragma unroll
    for (int j = 0; j < 16; j++) {
        int t = tid + j * 128;
        int r = t >> 5, seg = t & 31;
        uint32_t dst = sKh + (uint32_t)(((seg >> 3) * 64 + r) * 128)
                     + ((uint32_t)((seg & 7) * 16) ^ (((uint32_t)r & 7u) << 4));
        const float* g = K + (size_t)(kt + r) * CH + h * HD + seg * 4;
        CP_ASYNC16(dst, g);
    }
    // Vt tile: 128 rows (d) x 64 floats -> 2 chunks [128][32]
#pragma unroll
    for (int j = 0; j < 16; j++) {
        int t = tid + j * 128;
        int r = t >> 4, seg = t & 15;
        uint32_t dst = sVh + (uint32_t)(((seg >> 3) * 128 + r) * 128)
                     + ((uint32_t)((seg & 7) * 16) ^ (((uint32_t)r & 7u) << 4));
        const float* g = Vt + (size_t)(h * HD + r) * SEQ + kt + seg * 4;
        CP_ASYNC16(dst, g);
    }
    CP_COMMIT();
}

__device__ __forceinline__ void f_split_kv(
    float* sm, int tid)
{
    // Khi region floats [8192, 16384) -> split into Khi/Klo
    float4* kh = (float4*)(sm + 8192);
    float4* kl = (float4*)(sm + 16384);
#pragma unroll
    for (int j = 0; j < 16; j++) {
        int idx = tid + j * 128;
        float4 v = kh[idx];
        float4 hi, lo;
        hi.x = round_tf32_rna(v.x); lo.x = round_tf32_rna(v.x - hi.x);
        hi.y = round_tf32_rna(v.y); lo.y = round_tf32_rna(v.y - hi.y);
        hi.z = round_tf32_rna(v.z); lo.z = round_tf32_rna(v.z - hi.z);
        hi.w = round_tf32_rna(v.w); lo.w = round_tf32_rna(v.w - hi.w);
        kh[idx] = hi; kl[idx] = lo;
    }
    float4* vh = (float4*)(sm + 24576);
    float4* vl = (float4*)(sm + 32768);
#pragma unroll
    for (int j = 0; j < 16; j++) {
        int idx = tid + j * 128;
        float4 v = vh[idx];
        float4 hi, lo;
        hi.x = round_tf32_rna(v.x); lo.x = round_tf32_rna(v.x - hi.x);
        hi.y = round_tf32_rna(v.y); lo.y = round_tf32_rna(v.y - hi.y);
        hi.z = round_tf32_rna(v.z); lo.z = round_tf32_rna(v.z - hi.z);
        hi.w = round_tf32_rna(v.w); lo.w = round_tf32_rna(v.w - hi.w);
        vh[idx] = hi; vl[idx] = lo;
    }
}

__global__ void __launch_bounds__(128, 1)
flash_mma(const float* __restrict__ Q, const float* __restrict__ K,
          const float* __restrict__ Vt, float* __restrict__ O)
{
    extern __shared__ float sm[];
    const uint32_t sb  = smem_u32(sm);
    const uint32_t sQ  = sb;
    const uint32_t sKh = sb + 8192 * 4;
    const uint32_t sVh = sb + 24576 * 4;
    const uint32_t sP  = sb + 40960 * 4;
    const uint32_t KHL = 8192 * 4;      // Khi -> Klo byte offset
    const uint32_t VHL = 8192 * 4;      // Vthi -> Vtlo byte offset

    const int h   = blockIdx.y;
    const int q0  = blockIdx.x * BRF;
    const int tid = threadIdx.x;
    const int wid = tid >> 5, lane = tid & 31;
    const int gid = lane >> 2, tig = lane & 3;
    const float scale = 0.088388347648318447f;   // 1/sqrt(128)

    const int a_row = (lane & 7) + ((lane >> 3) & 1) * 8;
    const int a_cb  = ((lane >> 4) & 1) * 16;
    const int b_row = (lane & 7) + ((lane >> 4) & 1) * 8;
    const int b_cb  = ((lane >> 3) & 1) * 16;

    // Load Q (once) + first K/Vt tile
#pragma unroll
    for (int j = 0; j < 16; j++) {
        int t = tid + j * 128;
        int r = t >> 5, seg = t & 31;
        uint32_t dst = sQ + (uint32_t)(((seg >> 3) * 64 + r) * 128)
                     + ((uint32_t)((seg & 7) * 16) ^ (((uint32_t)r & 7u) << 4));
        const float* g = Q + (size_t)(q0 + r) * CH + h * HD + seg * 4;
        CP_ASYNC16(dst, g);
    }
    f_load_kv(K, Vt, h, 0, sKh, sVh, tid);
    CP_WAIT0();
    __syncthreads();
    f_split_kv(sm, tid);
    __syncthreads();

    float mrow[2] = {-INFINITY, -INFINITY};
    float lrow[2] = {0.f, 0.f};
    float o[16][4];
#pragma unroll
    for (int ni = 0; ni < 16; ni++)
#pragma unroll
        for (int r = 0; r < 4; r++) o[ni][r] = 0.f;

    for (int kt = 0; kt < SEQ; kt += BCF) {
        // ----- QK^T (split tf32): sc[m16][n64] -----
        float sc[8][4];
#pragma unroll
        for (int ni = 0; ni < 8; ni++)
#pragma unroll
            for (int r = 0; r < 4; r++) sc[ni][r] = 0.f;

#pragma unroll 4
        for (int ks = 0; ks < 16; ks++) {
            const int chunk = ks >> 2;
            const uint32_t kb = (uint32_t)((ks & 3) * 32);
            // A fragment (q, fp32 -> split in-register)
            uint32_t af[4], ah[4], al[4];
            {
                int row = wid * 16 + a_row;
                uint32_t addr = sQ + (uint32_t)((chunk * 64 + row) * 128)
                              + ((kb + a_cb) ^ (((uint32_t)row & 7u) << 4));
                LDMATRIX_X4(af[0], af[1], af[2], af[3], addr);
#pragma unroll
                for (int i = 0; i < 4; i++) {
                    float v = __uint_as_float(af[i]);
                    float hv = round_tf32_rna(v);
                    ah[i] = __float_as_uint(hv);
                    al[i] = __float_as_uint(round_tf32_rna(v - hv));
                }
            }
#pragma unroll
            for (int p = 0; p < 4; p++) {
                int row = p * 16 + b_row;
                uint32_t off = (uint32_t)((chunk * 64 + row) * 128)
                             + ((kb + b_cb) ^ (((uint32_t)row & 7u) << 4));
                uint32_t bh[4], bl[4];
                LDMATRIX_X4(bh[0], bh[1], bh[2], bh[3], sKh + off);
                LDMATRIX_X4(bl[0], bl[1], bl[2], bl[3], sKh + KHL + off);
                MMA_TF32(sc[2 * p],     ah, bh[0], bh[1]);
                MMA_TF32(sc[2 * p],     ah, bl[0], bl[1]);
                MMA_TF32(sc[2 * p],     al, bh[0], bh[1]);
                MMA_TF32(sc[2 * p + 1], ah, bh[2], bh[3]);
                MMA_TF32(sc[2 * p + 1], ah, bl[2], bl[3]);
                MMA_TF32(sc[2 * p + 1], al, bh[2], bh[3]);
            }
        }

        // ----- online softmax (fp32) -----
#pragma unroll
        for (int ni = 0; ni < 8; ni++)
#pragma unroll
            for (int r = 0; r < 4; r++) sc[ni][r] *= scale;

#pragma unroll
        for (int rr = 0; rr < 2; rr++) {
            float rm = -INFINITY;
#pragma unroll
            for (int ni = 0; ni < 8; ni++)
                rm = fmaxf(rm, fmaxf(sc[ni][rr * 2], sc[ni][rr * 2 + 1]));
            rm = fmaxf(rm, __shfl_xor_sync(0xffffffffu, rm, 1));
            rm = fmaxf(rm, __shfl_xor_sync(0xffffffffu, rm, 2));
            float mn = fmaxf(mrow[rr], rm);
            float alpha = __expf(mrow[rr] - mn);
            float rs = 0.f;
#pragma unroll
            for (int ni = 0; ni < 8; ni++) {
                float p0 = __expf(sc[ni][rr * 2]     - mn);
                float p1 = __expf(sc[ni][rr * 2 + 1] - mn);
                sc[ni][rr * 2] = p0; sc[ni][rr * 2 + 1] = p1;
                rs += p0 + p1;
            }
            rs += __shfl_xor_sync(0xffffffffu, rs, 1);
            rs += __shfl_xor_sync(0xffffffffu, rs, 2);
            lrow[rr] = lrow[rr] * alpha + rs;
            mrow[rr] = mn;
#pragma unroll
            for (int ni = 0; ni < 16; ni++) {
                o[ni][rr * 2]     *= alpha;
                o[ni][rr * 2 + 1] *= alpha;
            }
        }

        // ----- store P (fp32) to smem, warp-private rows -----
#pragma unroll
        for (int rr = 0; rr < 2; rr++) {
            int m = wid * 16 + gid + rr * 8;
#pragma unroll
            for (int ni = 0; ni < 8; ni++) {
                int c = ni * 8 + tig * 2;
                uint32_t addr = sP + (uint32_t)((((c >> 5) * 64) + m) * 128)
                              + (((uint32_t)(c & 31) * 4) ^ (((uint32_t)m & 7u) << 4));
                float2 pv = make_float2(sc[ni][rr * 2], sc[ni][rr * 2 + 1]);
                *(float2*)((char*)sm + (addr - sb)) = pv;
            }
        }
        __syncwarp();

        // ----- P @ V (split tf32): o[m16][d128] -----
#pragma unroll 4
        for (int ks = 0; ks < 8; ks++) {
            const int chunk = ks >> 2;
            const uint32_t kb = (uint32_t)((ks & 3) * 32);
            uint32_t pf[4], ph[4], pl[4];
            {
                int row = wid * 16 + a_row;
                uint32_t addr = sP + (uint32_t)((chunk * 64 + row) * 128)
                              + ((kb + a_cb) ^ (((uint32_t)row & 7u) << 4));
                LDMATRIX_X4(pf[0], pf[1], pf[2], pf[3], addr);
#pragma unroll
                for (int i = 0; i < 4; i++) {
                    float v = __uint_as_float(pf[i]);
                    float hv = round_tf32_rna(v);
                    ph[i] = __float_as_uint(hv);
                    pl[i] = __float_as_uint(round_tf32_rna(v - hv));
                }
            }
#pragma unroll
            for (int p = 0; p < 8; p++) {
                int row = p * 16 + b_row;
                uint32_t off = (uint32_t)((chunk * 128 + row) * 128)
                             + ((kb + b_cb) ^ (((uint32_t)row & 7u) << 4));
                uint32_t vh[4], vl[4];
                LDMATRIX_X4(vh[0], vh[1], vh[2], vh[3], sVh + off);
                LDMATRIX_X4(vl[0], vl[1], vl[2], vl[3], sVh + VHL + off);
                MMA_TF32(o[2 * p],     ph, vh[0], vh[1]);
                MMA_TF32(o[2 * p],     ph, vl[0], vl[1]);
                MMA_TF32(o[2 * p],     pl, vh[0], vh[1]);
                MMA_TF32(o[2 * p + 1], ph, vh[2], vh[3]);
                MMA_TF32(o[2 * p + 1], ph, vl[2], vl[3]);
                MMA_TF32(o[2 * p + 1], pl, vh[2], vh[3]);
            }
        }

        __syncthreads();
        if (kt + BCF < SEQ) {
            f_load_kv(K, Vt, h, kt + BCF, sKh, sVh, tid);
            CP_WAIT0();
            __syncthreads();
            f_split_kv(sm, tid);
            __syncthreads();
        }
    }

    // ----- epilogue: normalize, round to tf32, store -----
#pragma unroll
    for (int rr = 0; rr < 2; rr++) {
        float invl = 1.f / lrow[rr];
        int r = q0 + wid * 16 + gid + rr * 8;
#pragma unroll
        for (int ni = 0; ni < 16; ni++) {
            int c = h * HD + ni * 8 + tig * 2;
            float2 v;
            v.x = round_tf32_rna(o[ni][rr * 2]     * invl);
            v.y = round_tf32_rna(o[ni][rr * 2 + 1] * invl);
            *(float2*)(O + (size_t)r * CH + c) = v;
        }
    }
}

// ===========================================================================
extern "C" void kernel_launch(void* const* d_in, const int* in_sizes, int n_in,
                              void* d_out, int out_size)
{
    (void)in_sizes; (void)n_in; (void)out_size;
    const float* x    = (const float*)d_in[0];
    const float* rope = (const float*)d_in[1];
    const float* Wq   = (const float*)d_in[2];
    const float* bq   = (const float*)d_in[3];
    const float* Wk   = (const float*)d_in[4];
    const float* bk   = (const float*)d_in[5];
    const float* Wv   = (const float*)d_in[6];
    const float* bv   = (const float*)d_in[7];
    const float* qn   = (const float*)d_in[8];
    const float* kn   = (const float*)d_in[9];
    const float* Wo   = (const float*)d_in[10];
    const float* bo   = (const float*)d_in[11];
    float* out = (float*)d_out;

    float *gq, *gk, *gv, *gvt, *ga, *gxr, *gwq, *gwk, *gwv, *gwo;
    cudaGetSymbolAddress((void**)&gq,  g_q);
    cudaGetSymbolAddress((void**)&gk,  g_k);
    cudaGetSymbolAddress((void**)&gv,  g_v);
    cudaGetSymbolAddress((void**)&gvt, g_vt);
    cudaGetSymbolAddress((void**)&ga,  g_attn);
    cudaGetSymbolAddress((void**)&gxr, g_xr);
    cudaGetSymbolAddress((void**)&gwq, g_wqr);
    cudaGetSymbolAddress((void**)&gwk, g_wkr);
    cudaGetSymbolAddress((void**)&gwv, g_wvr);
    cudaGetSymbolAddress((void**)&gwo, g_wor);

    cudaFuncSetAttribute(gemm_mma_tf32,
        cudaFuncAttributeMaxDynamicSharedMemorySize, GSMEM_BYTES);
    cudaFuncSetAttribute(flash_mma,
        cudaFuncAttributeMaxDynamicSharedMemorySize, F_SMEM_BYTES);

    // Pre-round GEMM inputs to tf32 (RNA)
    const int n4x = SEQ * CH / 4, n4w = CH * CH / 4;
    round_tf32_kernel<<<(n4x + 255) / 256, 256>>>(x,  gxr, n4x);
    round_tf32_kernel<<<(n4w + 255) / 256, 256>>>(Wq, gwq, n4w);
    round_tf32_kernel<<<(n4w + 255) / 256, 256>>>(Wk, gwk, n4w);
    round_tf32_kernel<<<(n4w + 255) / 256, 256>>>(Wv, gwv, n4w);
    round_tf32_kernel<<<(n4w + 255) / 256, 256>>>(Wo, gwo, n4w);

    dim3 gg(CH / GBN, SEQ / GBM);
    gemm_mma_tf32<<<gg, 256, GSMEM_BYTES>>>(gxr, gwq, bq, gq, SEQ, CH, CH);
    gemm_mma_tf32<<<gg, 256, GSMEM_BYTES>>>(gxr, gwk, bk, gk, SEQ, CH, CH);
    gemm_mma_tf32<<<gg, 256, GSMEM_BYTES>>>(gxr, gwv, bv, gv, SEQ, CH, CH);

    rmsnorm_rope<<<SEQ * NH / 8, 256>>>(gq, qn, rope);
    rmsnorm_rope<<<SEQ * NH / 8, 256>>>(gk, kn, rope);

    // Transpose V for the PV mma (contraction dim contiguous)
    transpose_kernel<<<dim3(CH / 32, SEQ / 32), dim3(32, 8)>>>(gv, gvt);

    flash_mma<<<dim3(SEQ / BRF, NH), 128, F_SMEM_BYTES>>>(gq, gk, gvt, ga);

    gemm_mma_tf32<<<gg, 256, GSMEM_BYTES>>>(ga, gwo, bo, out, SEQ, CH, CH);
}

// round 16
// speedup vs baseline: 3.0694x; 1.0550x over previous
#include <cuda_runtime.h>
#include <cuda_fp16.h>
#include <cstdint>
#include <math.h>

#define SEQ 4096
#define CH  2048
#define NH  16
#define HD  128
#define EPSF 1.1920929e-07f

// ---- scratch (allocation-free __device__ globals) ----
__device__ __half s_xh[SEQ * CH], s_xl[SEQ * CH];
__device__ __half s_wqh[CH * CH], s_wql[CH * CH];
__device__ __half s_wkh[CH * CH], s_wkl[CH * CH];
__device__ __half s_wvh[CH * CH], s_wvl[CH * CH];
__device__ __half s_woh[CH * CH], s_wol[CH * CH];
__device__ float  g_qf[SEQ * CH], g_kf[SEQ * CH], g_vf[SEQ * CH];
__device__ __half s_qh[SEQ * CH], s_ql[SEQ * CH];
__device__ __half s_kh[SEQ * CH], s_kl[SEQ * CH];
__device__ __half s_vth[CH * SEQ], s_vtl[CH * SEQ];   // V^T [d][s]
__device__ __half s_ah[SEQ * CH], s_al[SEQ * CH];     // attention out

// ===========================================================================
// Helpers
// ===========================================================================
__device__ __forceinline__ uint32_t smem_u32(const void* p) {
    uint32_t a;
    asm("{ .reg .u64 t; cvta.to.shared.u64 t, %1; cvt.u32.u64 %0, t; }"
        : "=r"(a) : "l"(p));
    return a;
}

#define LDMATRIX_X4(r0, r1, r2, r3, addr)                                     \
    asm volatile("ldmatrix.sync.aligned.m8n8.x4.shared.b16 {%0,%1,%2,%3}, [%4];" \
                 : "=r"(r0), "=r"(r1), "=r"(r2), "=r"(r3) : "r"(addr))

#define MMA_F16(d, a, b0, b1)                                                 \
    asm volatile(                                                             \
        "mma.sync.aligned.m16n8k16.row.col.f32.f16.f16.f32 "                  \
        "{%0,%1,%2,%3}, {%4,%5,%6,%7}, {%8,%9}, {%0,%1,%2,%3};"               \
        : "+f"((d)[0]), "+f"((d)[1]), "+f"((d)[2]), "+f"((d)[3])              \
        : "r"((a)[0]), "r"((a)[1]), "r"((a)[2]), "r"((a)[3]),                 \
          "r"(b0), "r"(b1))

#define CP_ASYNC16(dst, src)                                                  \
    asm volatile("cp.async.cg.shared.global [%0], [%1], 16;"                  \
                 :: "r"(dst), "l"(src))
#define CP_COMMIT()  asm volatile("cp.async.commit_group;" ::: "memory")
#define CP_WAIT(n)   asm volatile("cp.async.wait_group %0;" :: "n"(n) : "memory")

__device__ __forceinline__ uint32_t pack_h2(__half a, __half b) {
    __half2 h = __halves2half2(a, b);
    return *(uint32_t*)&h;
}

// ===========================================================================
// fp32 -> split fp16 (hi = rn(x), lo = rn(x - hi)); 4 elems/thread
// ===========================================================================
__global__ void f32_split(const float* __restrict__ in,
                          __half* __restrict__ oh, __half* __restrict__ ol,
                          int n4)
{
    int i = blockIdx.x * blockDim.x + threadIdx.x;
    if (i >= n4) return;
    float4 v = ((const float4*)in)[i];
    __half h0 = __float2half_rn(v.x), h1 = __float2half_rn(v.y);
    __half h2 = __float2half_rn(v.z), h3 = __float2half_rn(v.w);
    uint2 hh, ll;
    hh.x = pack_h2(h0, h1); hh.y = pack_h2(h2, h3);
    ll.x = pack_h2(__float2half_rn(v.x - __half2float(h0)),
                   __float2half_rn(v.y - __half2float(h1)));
    ll.y = pack_h2(__float2half_rn(v.z - __half2float(h2)),
                   __float2half_rn(v.w - __half2float(h3)));
    *(uint2*)(oh + 4 * (size_t)i) = hh;
    *(uint2*)(ol + 4 * (size_t)i) = ll;
}

// ===========================================================================
// fp32 [SEQ][CH] -> split fp16 transposed [CH][SEQ]
// ===========================================================================
__global__ void transpose_split(const float* __restrict__ in,
                                __half* __restrict__ oh, __half* __restrict__ ol)
{
    __shared__ float t[32][33];
    int bx = blockIdx.x * 32;   // d
    int by = blockIdx.y * 32;   // s
    int x = threadIdx.x, y = threadIdx.y;
#pragma unroll
    for (int i = 0; i < 32; i += 8)
        t[y + i][x] = in[(size_t)(by + y + i) * CH + bx + x];
    __syncthreads();
#pragma unroll
    for (int i = 0; i < 32; i += 8) {
        float v = t[x][y + i];
        __half h = __float2half_rn(v);
        size_t idx = (size_t)(bx + y + i) * SEQ + by + x;
        oh[idx] = h;
        ol[idx] = __float2half_rn(v - __half2float(h));
    }
}

// ===========================================================================
// Split-fp16 GEMM: Out[m,n] = sum_k A[m,k]*B[n,k] + bias[n]   (fp32 out)
// A,B given as (hi,lo) fp16 pairs. 3-MMA scheme: AhBh + AhBl + AlBh.
// CTA 128x128, K-chunk 64, 8 warps (2x4), double-buffered cp.async.
// smem/stage: Ah,Al,Bh,Bl x 16KB = 64KB; 2 stages = 128KB.
// ===========================================================================
#define GBM 128
#define GBN 128
#define GCK 64
#define GST 65536                      // stage stride bytes
#define GSMEM_BYTES (2 * GST)

__device__ __forceinline__ void gs_load(
    const __half* __restrict__ Ah, const __half* __restrict__ Al,
    const __half* __restrict__ Bh, const __half* __restrict__ Bl,
    int bm, int bn, int K, int k0, uint32_t s0, int tid)
{
#pragma unroll
    for (int t = 0; t < 4; t++) {
        int s = tid + t * 256;
        int r = s >> 3, seg = s & 7;
        uint32_t sw = (uint32_t)(r * 128) + (((uint32_t)seg * 16) ^ (((uint32_t)r & 7u) << 4));
        size_t ao = (size_t)(bm + r) * K + k0 + seg * 8;
        size_t bo = (size_t)(bn + r) * K + k0 + seg * 8;
        CP_ASYNC16(s0 + sw,         Ah + ao);
        CP_ASYNC16(s0 + 16384 + sw, Al + ao);
        CP_ASYNC16(s0 + 32768 + sw, Bh + bo);
        CP_ASYNC16(s0 + 49152 + sw, Bl + bo);
    }
    CP_COMMIT();
}

__global__ void __launch_bounds__(256)
gemm_split(const __half* __restrict__ Ah, const __half* __restrict__ Al,
           const __half* __restrict__ Bh, const __half* __restrict__ Bl,
           const float* __restrict__ bias, float* __restrict__ Out,
           int M, int N, int K)
{
    extern __shared__ char smem[];
    const uint32_t sb = smem_u32(smem);
    const int tid  = threadIdx.x;
    const int wid  = tid >> 5;
    const int lane = tid & 31;
    const int bm = blockIdx.y * GBM;
    const int bn = blockIdx.x * GBN;
    const int wm = wid >> 2;
    const int wn = wid & 3;
    const int NCHUNK = K / GCK;

    const int a_row = wm * 64 + (lane & 7) + ((lane >> 3) & 1) * 8;
    const int a_cb  = ((lane >> 4) & 1) * 16;
    const int b_row = wn * 32 + (lane & 7) + ((lane >> 4) & 1) * 8;
    const int b_cb  = ((lane >> 3) & 1) * 16;

    float d[4][4][4];
#pragma unroll
    for (int mi = 0; mi < 4; mi++)
#pragma unroll
        for (int ni = 0; ni < 4; ni++)
#pragma unroll
            for (int r = 0; r < 4; r++) d[mi][ni][r] = 0.f;

    gs_load(Ah, Al, Bh, Bl, bm, bn, K, 0,   sb,       tid);
    gs_load(Ah, Al, Bh, Bl, bm, bn, K, GCK, sb + GST, tid);

    for (int i = 0; i < NCHUNK; i++) {
        const int b = i & 1;
        if (i >= NCHUNK - 2) CP_WAIT(0);
        else                 CP_WAIT(1);
        __syncthreads();

        const uint32_t S = sb + (b ? GST : 0);

#pragma unroll
        for (int ks = 0; ks < 4; ks++) {
            uint32_t ah[4][4], al[4][4], bh[2][4], bl[2][4];
#pragma unroll
            for (int mi = 0; mi < 4; mi++) {
                int row = a_row + mi * 16;
                uint32_t off = (uint32_t)row * 128 +
                    ((uint32_t)(ks * 32 + a_cb) ^ (((uint32_t)row & 7u) << 4));
                LDMATRIX_X4(ah[mi][0], ah[mi][1], ah[mi][2], ah[mi][3], S + off);
                LDMATRIX_X4(al[mi][0], al[mi][1], al[mi][2], al[mi][3], S + 16384 + off);
            }
#pragma unroll
            for (int p = 0; p < 2; p++) {
                int row = b_row + p * 16;
                uint32_t off = (uint32_t)row * 128 +
                    ((uint32_t)(ks * 32 + b_cb) ^ (((uint32_t)row & 7u) << 4));
                LDMATRIX_X4(bh[p][0], bh[p][1], bh[p][2], bh[p][3], S + 32768 + off);
                LDMATRIX_X4(bl[p][0], bl[p][1], bl[p][2], bl[p][3], S + 49152 + off);
            }
#pragma unroll
            for (int mi = 0; mi < 4; mi++) {
#pragma unroll
                for (int p = 0; p < 2; p++) {
                    MMA_F16(d[mi][2 * p],     ah[mi], bh[p][0], bh[p][1]);
                    MMA_F16(d[mi][2 * p],     ah[mi], bl[p][0], bl[p][1]);
                    MMA_F16(d[mi][2 * p],     al[mi], bh[p][0], bh[p][1]);
                    MMA_F16(d[mi][2 * p + 1], ah[mi], bh[p][2], bh[p][3]);
                    MMA_F16(d[mi][2 * p + 1], ah[mi], bl[p][2], bl[p][3]);
                    MMA_F16(d[mi][2 * p + 1], al[mi], bh[p][2], bh[p][3]);
                }
            }
        }
        __syncthreads();

        if (i + 2 < NCHUNK)
            gs_load(Ah, Al, Bh, Bl, bm, bn, K, (i + 2) * GCK,
                    sb + (b ? GST : 0), tid);
    }

    const int gid = lane >> 2, tig = lane & 3;
#pragma unroll
    for (int mi = 0; mi < 4; mi++) {
#pragma unroll
        for (int ni = 0; ni < 4; ni++) {
            int r0 = bm + wm * 64 + mi * 16 + gid;
            int c  = bn + wn * 32 + ni * 8 + tig * 2;
            float bx = bias[c], by = bias[c + 1];
            *(float2*)(Out + (size_t)r0 * N + c) =
                make_float2(d[mi][ni][0] + bx, d[mi][ni][1] + by);
            *(float2*)(Out + (size_t)(r0 + 8) * N + c) =
                make_float2(d[mi][ni][2] + bx, d[mi][ni][3] + by);
        }
    }
}

// ===========================================================================
// RMSNorm + rotary on fp32 input -> split fp16 output. One warp per row.
// ===========================================================================
__global__ void rmsnorm_rope_split(const float* __restrict__ qf,
                                   __half* __restrict__ oh, __half* __restrict__ ol,
                                   const float* __restrict__ w,
                                   const float* __restrict__ rope)
{
    int gwarp = (blockIdx.x * blockDim.x + threadIdx.x) >> 5;
    int lane  = threadIdx.x & 31;
    if (gwarp >= SEQ * NH) return;
    int s = gwarp / NH;

    const float* row = qf + (size_t)gwarp * HD;
    float4 v = *(const float4*)(row + lane * 4);
    float ss = v.x * v.x + v.y * v.y + v.z * v.z + v.w * v.w;
#pragma unroll
    for (int m = 16; m; m >>= 1) ss += __shfl_xor_sync(0xffffffffu, ss, m);
    float inv = rsqrtf(ss * (1.0f / HD) + EPSF);

    float4 wv = *(const float4*)(w + lane * 4);
    float x0 = v.x * inv * wv.x;
    float x1 = v.y * inv * wv.y;
    float x2 = v.z * inv * wv.z;
    float x3 = v.w * inv * wv.w;

    const float* rp = rope + (size_t)s * 256 + (size_t)(2 * lane) * 4;
    float4 r0 = *(const float4*)rp;
    float4 r1 = *(const float4*)(rp + 4);
    float o0 = r0.x * x0 + r0.y * x1;
    float o1 = r0.z * x0 + r0.w * x1;
    float o2 = r1.x * x2 + r1.y * x3;
    float o3 = r1.z * x2 + r1.w * x3;

    __half h0 = __float2half_rn(o0), h1 = __float2half_rn(o1);
    __half h2 = __float2half_rn(o2), h3 = __float2half_rn(o3);
    uint2 hh, ll;
    hh.x = pack_h2(h0, h1); hh.y = pack_h2(h2, h3);
    ll.x = pack_h2(__float2half_rn(o0 - __half2float(h0)),
                   __float2half_rn(o1 - __half2float(h1)));
    ll.y = pack_h2(__float2half_rn(o2 - __half2float(h2)),
                   __float2half_rn(o3 - __half2float(h3)));
    size_t base = (size_t)gwarp * HD + lane * 4;
    *(uint2*)(oh + base) = hh;
    *(uint2*)(ol + base) = ll;
}

// ===========================================================================
// Flash attention, split-fp16 (3-MMA) for QK^T and PV; P kept in registers.
// BR=128, BC=64, 256 threads (8 warps; warp w owns q-rows [w*16, w*16+16)).
// smem: Qh 32K @0, Ql 32K @32768;
//       stage s (s=0,1) @ 65536+s*65536: Kh 16K, Kl 16K, Vh 16K, Vl 16K.
// Total 192 KB.
// ===========================================================================
#define FBR 128
#define FST(s) (65536 + (s) * 65536)
#define F_SMEM_BYTES 196608

__device__ __forceinline__ void f_load_kv(
    const __half* __restrict__ Kh, const __half* __restrict__ Kl,
    const __half* __restrict__ Vth, const __half* __restrict__ Vtl,
    int h, int kt, uint32_t st, int tid)
{
    // K tiles: 64 key-rows x 128 fp16 -> [2ck][64][128B] each (hi @+0, lo @+16384)
#pragma unroll
    for (int j = 0; j < 4; j++) {
        int t = tid + j * 256;
        int r = t >> 4, idx = t & 15;
        int ck = idx >> 3, seg = idx & 7;
        uint32_t dst = st + (uint32_t)(ck * 8192 + r * 128)
                     + (((uint32_t)seg * 16) ^ (((uint32_t)r & 7u) << 4));
        size_t src = (size_t)(kt + r) * CH + h * HD + ck * 64 + seg * 8;
        CP_ASYNC16(dst,         Kh + src);
        CP_ASYNC16(dst + 16384, Kl + src);
    }
    // Vt tiles: 128 d-rows x 64 fp16 -> [128][128B] (hi @+32768, lo @+49152)
#pragma unroll
    for (int j = 0; j < 4; j++) {
        int t = tid + j * 256;
        int r = t >> 3, seg = t & 7;
        uint32_t dst = st + 32768 + (uint32_t)(r * 128)
                     + (((uint32_t)seg * 16) ^ (((uint32_t)r & 7u) << 4));
        size_t src = (size_t)(h * HD + r) * SEQ + kt + seg * 8;
        CP_ASYNC16(dst,         Vth + src);
        CP_ASYNC16(dst + 16384, Vtl + src);
    }
}

__global__ void __launch_bounds__(256)
flash_split(const __half* __restrict__ Qh, const __half* __restrict__ Ql,
            const __half* __restrict__ Kh, const __half* __restrict__ Kl,
            const __half* __restrict__ Vth, const __half* __restrict__ Vtl,
            __half* __restrict__ Oh, __half* __restrict__ Ol)
{
    extern __shared__ char smem[];
    const uint32_t sb = smem_u32(smem);

    const int h   = blockIdx.y;
    const int q0  = blockIdx.x * FBR;
    const int tid = threadIdx.x;
    const int wid = tid >> 5, lane = tid & 31;
    const int gid = lane >> 2, tig = lane & 3;
    const float scale = 0.088388347648318447f;   // 1/sqrt(128)

    const int a_row = wid * 16 + (lane & 7) + ((lane >> 3) & 1) * 8;
    const int a_cb  = ((lane >> 4) & 1) * 16;
    const int b_row = (lane & 7) + ((lane >> 4) & 1) * 8;
    const int b_cb  = ((lane >> 3) & 1) * 16;

    // Q load: [2ck][128][128B] hi @0, lo @32768
#pragma unroll
    for (int j = 0; j < 8; j++) {
        int t = tid + j * 256;
        int r = t >> 4, idx = t & 15;
        int ck = idx >> 3, seg = idx & 7;
        uint32_t dst = sb + (uint32_t)(ck * 16384 + r * 128)
                     + (((uint32_t)seg * 16) ^ (((uint32_t)r & 7u) << 4));
        size_t src = (size_t)(q0 + r) * CH + h * HD + ck * 64 + seg * 8;
        CP_ASYNC16(dst,         Qh + src);
        CP_ASYNC16(dst + 32768, Ql + src);
    }
    f_load_kv(Kh, Kl, Vth, Vtl, h, 0, sb + FST(0), tid);
    CP_COMMIT();

    float mrow[2] = {-INFINITY, -INFINITY};
    float lrow[2] = {0.f, 0.f};
    float o[16][4];
#pragma unroll
    for (int ni = 0; ni < 16; ni++)
#pragma unroll
        for (int r = 0; r < 4; r++) o[ni][r] = 0.f;

    for (int it = 0; it < SEQ / 64; it++) {
        const int b = it & 1;
        if (it + 1 < SEQ / 64) {
            f_load_kv(Kh, Kl, Vth, Vtl, h, (it + 1) * 64, sb + FST(b ^ 1), tid);
            CP_COMMIT();
            CP_WAIT(1);
        } else {
            CP_WAIT(0);
        }
        __syncthreads();

        const uint32_t SK = sb + FST(b);
        const uint32_t SV = SK + 32768;

        // ----- QK^T (split): sc[m16][n64] -----
        float sc[8][4];
#pragma unroll
        for (int ni = 0; ni < 8; ni++)
#pragma unroll
            for (int r = 0; r < 4; r++) sc[ni][r] = 0.f;

#pragma unroll
        for (int ks = 0; ks < 8; ks++) {
            const int ck = ks >> 2;
            const uint32_t kb = (uint32_t)((ks & 3) * 32);
            uint32_t qh[4], ql[4];
            {
                uint32_t off = (uint32_t)(ck * 16384 + a_row * 128)
                             + ((kb + a_cb) ^ (((uint32_t)a_row & 7u) << 4));
                LDMATRIX_X4(qh[0], qh[1], qh[2], qh[3], sb + off);
                LDMATRIX_X4(ql[0], ql[1], ql[2], ql[3], sb + 32768 + off);
            }
#pragma unroll
            for (int p = 0; p < 4; p++) {
                int row = p * 16 + b_row;
                uint32_t off = (uint32_t)(ck * 8192 + row * 128)
                             + ((kb + b_cb) ^ (((uint32_t)row & 7u) << 4));
                uint32_t bh[4], bl[4];
                LDMATRIX_X4(bh[0], bh[1], bh[2], bh[3], SK + off);
                LDMATRIX_X4(bl[0], bl[1], bl[2], bl[3], SK + 16384 + off);
                MMA_F16(sc[2 * p],     qh, bh[0], bh[1]);
                MMA_F16(sc[2 * p],     qh, bl[0], bl[1]);
                MMA_F16(sc[2 * p],     ql, bh[0], bh[1]);
                MMA_F16(sc[2 * p + 1], qh, bh[2], bh[3]);
                MMA_F16(sc[2 * p + 1], qh, bl[2], bl[3]);
                MMA_F16(sc[2 * p + 1], ql, bh[2], bh[3]);
            }
        }

        // ----- online softmax (fp32) -----
#pragma unroll
        for (int ni = 0; ni < 8; ni++)
#pragma unroll
            for (int r = 0; r < 4; r++) sc[ni][r] *= scale;

#pragma unroll
        for (int rr = 0; rr < 2; rr++) {
            float rm = -INFINITY;
#pragma unroll
            for (int ni = 0; ni < 8; ni++)
                rm = fmaxf(rm, fmaxf(sc[ni][rr * 2], sc[ni][rr * 2 + 1]));
            rm = fmaxf(rm, __shfl_xor_sync(0xffffffffu, rm, 1));
            rm = fmaxf(rm, __shfl_xor_sync(0xffffffffu, rm, 2));
            float mn = fmaxf(mrow[rr], rm);
            float alpha = __expf(mrow[rr] - mn);
            float rs = 0.f;
#pragma unroll
            for (int ni = 0; ni < 8; ni++) {
                float p0 = __expf(sc[ni][rr * 2]     - mn);
                float p1 = __expf(sc[ni][rr * 2 + 1] - mn);
                sc[ni][rr * 2] = p0; sc[ni][rr * 2 + 1] = p1;
                rs += p0 + p1;
            }
            rs += __shfl_xor_sync(0xffffffffu, rs, 1);
            rs += __shfl_xor_sync(0xffffffffu, rs, 2);
            lrow[rr] = lrow[rr] * alpha + rs;
            mrow[rr] = mn;
#pragma unroll
            for (int ni = 0; ni < 16; ni++) {
                o[ni][rr * 2]     *= alpha;
                o[ni][rr * 2 + 1] *= alpha;
            }
        }

        // ----- P @ V (split): P A-fragments built in registers from sc -----
#pragma unroll
        for (int j = 0; j < 4; j++) {
            uint32_t ph[4], pl[4];
#pragma unroll
            for (int half = 0; half < 2; half++) {
                const float* s4 = sc[2 * j + half];
                __half h0 = __float2half_rn(s4[0]), h1 = __float2half_rn(s4[1]);
                __half h2 = __float2half_rn(s4[2]), h3 = __float2half_rn(s4[3]);
                ph[2 * half + 0] = pack_h2(h0, h1);   // a0 / a2: rows gid
                ph[2 * half + 1] = pack_h2(h2, h3);   // a1 / a3: rows gid+8
                pl[2 * half + 0] = pack_h2(__float2half_rn(s4[0] - __half2float(h0)),
                                           __float2half_rn(s4[1] - __half2float(h1)));
                pl[2 * half + 1] = pack_h2(__float2half_rn(s4[2] - __half2float(h2)),
                                           __float2half_rn(s4[3] - __half2float(h3)));
            }
            const uint32_t kb = (uint32_t)(j * 32);
#pragma unroll
            for (int p = 0; p < 8; p++) {
                int row = p * 16 + b_row;
                uint32_t off = (uint32_t)(row * 128)
                             + ((kb + b_cb) ^ (((uint32_t)row & 7u) << 4));
                uint32_t vh[4], vl[4];
                LDMATRIX_X4(vh[0], vh[1], vh[2], vh[3], SV + off);
                LDMATRIX_X4(vl[0], vl[1], vl[2], vl[3], SV + 16384 + off);
                MMA_F16(o[2 * p],     ph, vh[0], vh[1]);
                MMA_F16(o[2 * p],     ph, vl[0], vl[1]);
                MMA_F16(o[2 * p],     pl, vh[0], vh[1]);
                MMA_F16(o[2 * p + 1], ph, vh[2], vh[3]);
                MMA_F16(o[2 * p + 1], ph, vl[2], vl[3]);
                MMA_F16(o[2 * p + 1], pl, vh[2], vh[3]);
            }
        }
        __syncthreads();
    }

    // ----- epilogue: normalize, split to fp16 hi/lo -----
#pragma unroll
    for (int rr = 0; rr < 2; rr++) {
        float invl = 1.f / lrow[rr];
        int r = q0 + wid * 16 + gid + rr * 8;
#pragma unroll
        for (int ni = 0; ni < 16; ni++) {
            int c = h * HD + ni * 8 + tig * 2;
            float v0 = o[ni][rr * 2] * invl;
            float v1 = o[ni][rr * 2 + 1] * invl;
            __half h0 = __float2half_rn(v0), h1 = __float2half_rn(v1);
            *(uint32_t*)(Oh + (size_t)r * CH + c) = pack_h2(h0, h1);
            *(uint32_t*)(Ol + (size_t)r * CH + c) =
                pack_h2(__float2half_rn(v0 - __half2float(h0)),
                        __float2half_rn(v1 - __half2float(h1)));
        }
    }
}

// ===========================================================================
extern "C" void kernel_launch(void* const* d_in, const int* in_sizes, int n_in,
                              void* d_out, int out_size)
{
    (void)in_sizes; (void)n_in; (void)out_size;
    const float* x    = (const float*)d_in[0];
    const float* rope = (const float*)d_in[1];
    const float* Wq   = (const float*)d_in[2];
    const float* bq   = (const float*)d_in[3];
    const float* Wk   = (const float*)d_in[4];
    const float* bk   = (const float*)d_in[5];
    const float* Wv   = (const float*)d_in[6];
    const float* bv   = (const float*)d_in[7];
    const float* qn   = (const float*)d_in[8];
    const float* kn   = (const float*)d_in[9];
    const float* Wo   = (const float*)d_in[10];
    const float* bo   = (const float*)d_in[11];
    float* out = (float*)d_out;

    __half *xh, *xl, *wqh, *wql, *wkh, *wkl, *wvh, *wvl, *woh, *wol;
    __half *qh, *ql, *kh, *kl, *vth, *vtl, *ah, *al;
    float *qf, *kf, *vf;
    cudaGetSymbolAddress((void**)&xh,  s_xh);  cudaGetSymbolAddress((void**)&xl,  s_xl);
    cudaGetSymbolAddress((void**)&wqh, s_wqh); cudaGetSymbolAddress((void**)&wql, s_wql);
    cudaGetSymbolAddress((void**)&wkh, s_wkh); cudaGetSymbolAddress((void**)&wkl, s_wkl);
    cudaGetSymbolAddress((void**)&wvh, s_wvh); cudaGetSymbolAddress((void**)&wvl, s_wvl);
    cudaGetSymbolAddress((void**)&woh, s_woh); cudaGetSymbolAddress((void**)&wol, s_wol);
    cudaGetSymbolAddress((void**)&qf,  g_qf);  cudaGetSymbolAddress((void**)&kf,  g_kf);
    cudaGetSymbolAddress((void**)&vf,  g_vf);
    cudaGetSymbolAddress((void**)&qh,  s_qh);  cudaGetSymbolAddress((void**)&ql,  s_ql);
    cudaGetSymbolAddress((void**)&kh,  s_kh);  cudaGetSymbolAddress((void**)&kl,  s_kl);
    cudaGetSymbolAddress((void**)&vth, s_vth); cudaGetSymbolAddress((void**)&vtl, s_vtl);
    cudaGetSymbolAddress((void**)&ah,  s_ah);  cudaGetSymbolAddress((void**)&al,  s_al);

    cudaFuncSetAttribute(gemm_split,
        cudaFuncAttributeMaxDynamicSharedMemorySize, GSMEM_BYTES);
    cudaFuncSetAttribute(flash_split,
        cudaFuncAttributeMaxDynamicSharedMemorySize, F_SMEM_BYTES);

    // Split inputs into fp16 (hi, lo)
    const int n4x = SEQ * CH / 4, n4w = CH * CH / 4;
    f32_split<<<(n4x + 255) / 256, 256>>>(x,  xh,  xl,  n4x);
    f32_split<<<(n4w + 255) / 256, 256>>>(Wq, wqh, wql, n4w);
    f32_split<<<(n4w + 255) / 256, 256>>>(Wk, wkh, wkl, n4w);
    f32_split<<<(n4w + 255) / 256, 256>>>(Wv, wvh, wvl, n4w);
    f32_split<<<(n4w + 255) / 256, 256>>>(Wo, woh, wol, n4w);

    dim3 gg(CH / GBN, SEQ / GBM);
    gemm_split<<<gg, 256, GSMEM_BYTES>>>(xh, xl, wqh, wql, bq, qf, SEQ, CH, CH);
    gemm_split<<<gg, 256, GSMEM_BYTES>>>(xh, xl, wkh, wkl, bk, kf, SEQ, CH, CH);
    gemm_split<<<gg, 256, GSMEM_BYTES>>>(xh, xl, wvh, wvl, bv, vf, SEQ, CH, CH);

    rmsnorm_rope_split<<<SEQ * NH / 8, 256>>>(qf, qh, ql, qn, rope);
    rmsnorm_rope_split<<<SEQ * NH / 8, 256>>>(kf, kh, kl, kn, rope);

    transpose_split<<<dim3(CH / 32, SEQ / 32), dim3(32, 8)>>>(vf, vth, vtl);

    flash_split<<<dim3(SEQ / FBR, NH), 256, F_SMEM_BYTES>>>(
        qh, ql, kh, kl, vth, vtl, ah, al);

    gemm_split<<<gg, 256, GSMEM_BYTES>>>(ah, al, woh, wol, bo, out, SEQ, CH, CH);
}

// round 17
// speedup vs baseline: 5.5423x; 1.8057x over previous
#include <cuda_runtime.h>
#include <cuda_fp16.h>
#include <cstdint>
#include <math.h>

#define SEQ 4096
#define CH  2048
#define NH  16
#define HD  128
#define EPSF 1.1920929e-07f

// ---- scratch (allocation-free __device__ globals) ----
__device__ __half s_xh[SEQ * CH], s_xl[SEQ * CH];
__device__ __half s_wqh[CH * CH], s_wql[CH * CH];
__device__ __half s_wkh[CH * CH], s_wkl[CH * CH];
__device__ __half s_wvh[CH * CH], s_wvl[CH * CH];
__device__ __half s_woh[CH * CH], s_wol[CH * CH];
__device__ float  g_qf[SEQ * CH], g_kf[SEQ * CH], g_vf[SEQ * CH];
__device__ __half s_qh[SEQ * CH];                    // q plain fp16
__device__ __half s_kh[SEQ * CH], s_kl[SEQ * CH];    // k split
__device__ __half s_vth[CH * SEQ];                   // V^T plain [d][s]
__device__ __half s_ah[SEQ * CH], s_al[SEQ * CH];    // attention out (split)

// ===========================================================================
// Helpers
// ===========================================================================
__device__ __forceinline__ uint32_t smem_u32(const void* p) {
    uint32_t a;
    asm("{ .reg .u64 t; cvta.to.shared.u64 t, %1; cvt.u32.u64 %0, t; }"
        : "=r"(a) : "l"(p));
    return a;
}

#define LDMATRIX_X4(r0, r1, r2, r3, addr)                                     \
    asm volatile("ldmatrix.sync.aligned.m8n8.x4.shared.b16 {%0,%1,%2,%3}, [%4];" \
                 : "=r"(r0), "=r"(r1), "=r"(r2), "=r"(r3) : "r"(addr))

#define MMA_F16(d, a, b0, b1)                                                 \
    asm volatile(                                                             \
        "mma.sync.aligned.m16n8k16.row.col.f32.f16.f16.f32 "                  \
        "{%0,%1,%2,%3}, {%4,%5,%6,%7}, {%8,%9}, {%0,%1,%2,%3};"               \
        : "+f"((d)[0]), "+f"((d)[1]), "+f"((d)[2]), "+f"((d)[3])              \
        : "r"((a)[0]), "r"((a)[1]), "r"((a)[2]), "r"((a)[3]),                 \
          "r"(b0), "r"(b1))

#define CP_ASYNC16(dst, src)                                                  \
    asm volatile("cp.async.cg.shared.global [%0], [%1], 16;"                  \
                 :: "r"(dst), "l"(src))
#define CP_COMMIT()  asm volatile("cp.async.commit_group;" ::: "memory")
#define CP_WAIT(n)   asm volatile("cp.async.wait_group %0;" :: "n"(n) : "memory")

__device__ __forceinline__ uint32_t pack_h2(__half a, __half b) {
    __half2 h = __halves2half2(a, b);
    return *(uint32_t*)&h;
}

// ===========================================================================
// fp32 -> split fp16 (hi = rn(x), lo = rn(x - hi)); 4 elems/thread
// ===========================================================================
__global__ void f32_split(const float* __restrict__ in,
                          __half* __restrict__ oh, __half* __restrict__ ol,
                          int n4)
{
    int i = blockIdx.x * blockDim.x + threadIdx.x;
    if (i >= n4) return;
    float4 v = ((const float4*)in)[i];
    __half h0 = __float2half_rn(v.x), h1 = __float2half_rn(v.y);
    __half h2 = __float2half_rn(v.z), h3 = __float2half_rn(v.w);
    uint2 hh, ll;
    hh.x = pack_h2(h0, h1); hh.y = pack_h2(h2, h3);
    ll.x = pack_h2(__float2half_rn(v.x - __half2float(h0)),
                   __float2half_rn(v.y - __half2float(h1)));
    ll.y = pack_h2(__float2half_rn(v.z - __half2float(h2)),
                   __float2half_rn(v.w - __half2float(h3)));
    *(uint2*)(oh + 4 * (size_t)i) = hh;
    *(uint2*)(ol + 4 * (size_t)i) = ll;
}

// ===========================================================================
// fp32 [SEQ][CH] -> plain fp16 transposed [CH][SEQ]  (for V)
// ===========================================================================
__global__ void transpose_plain(const float* __restrict__ in,
                                __half* __restrict__ oh)
{
    __shared__ float t[32][33];
    int bx = blockIdx.x * 32;   // d
    int by = blockIdx.y * 32;   // s
    int x = threadIdx.x, y = threadIdx.y;
#pragma unroll
    for (int i = 0; i < 32; i += 8)
        t[y + i][x] = in[(size_t)(by + y + i) * CH + bx + x];
    __syncthreads();
#pragma unroll
    for (int i = 0; i < 32; i += 8)
        oh[(size_t)(bx + y + i) * SEQ + by + x] = __float2half_rn(t[x][y + i]);
}

// ===========================================================================
// Split-fp16 GEMM (3-MMA, unchanged): Out = A @ B^T + bias (fp32 out)
// ===========================================================================
#define GBM 128
#define GBN 128
#define GCK 64
#define GST 65536
#define GSMEM_BYTES (2 * GST)

__device__ __forceinline__ void gs_load(
    const __half* __restrict__ Ah, const __half* __restrict__ Al,
    const __half* __restrict__ Bh, const __half* __restrict__ Bl,
    int bm, int bn, int K, int k0, uint32_t s0, int tid)
{
#pragma unroll
    for (int t = 0; t < 4; t++) {
        int s = tid + t * 256;
        int r = s >> 3, seg = s & 7;
        uint32_t sw = (uint32_t)(r * 128) + (((uint32_t)seg * 16) ^ (((uint32_t)r & 7u) << 4));
        size_t ao = (size_t)(bm + r) * K + k0 + seg * 8;
        size_t bo = (size_t)(bn + r) * K + k0 + seg * 8;
        CP_ASYNC16(s0 + sw,         Ah + ao);
        CP_ASYNC16(s0 + 16384 + sw, Al + ao);
        CP_ASYNC16(s0 + 32768 + sw, Bh + bo);
        CP_ASYNC16(s0 + 49152 + sw, Bl + bo);
    }
    CP_COMMIT();
}

__global__ void __launch_bounds__(256)
gemm_split(const __half* __restrict__ Ah, const __half* __restrict__ Al,
           const __half* __restrict__ Bh, const __half* __restrict__ Bl,
           const float* __restrict__ bias, float* __restrict__ Out,
           int M, int N, int K)
{
    extern __shared__ char smem[];
    const uint32_t sb = smem_u32(smem);
    const int tid  = threadIdx.x;
    const int wid  = tid >> 5;
    const int lane = tid & 31;
    const int bm = blockIdx.y * GBM;
    const int bn = blockIdx.x * GBN;
    const int wm = wid >> 2;
    const int wn = wid & 3;
    const int NCHUNK = K / GCK;

    const int a_row = wm * 64 + (lane & 7) + ((lane >> 3) & 1) * 8;
    const int a_cb  = ((lane >> 4) & 1) * 16;
    const int b_row = wn * 32 + (lane & 7) + ((lane >> 4) & 1) * 8;
    const int b_cb  = ((lane >> 3) & 1) * 16;

    float d[4][4][4];
#pragma unroll
    for (int mi = 0; mi < 4; mi++)
#pragma unroll
        for (int ni = 0; ni < 4; ni++)
#pragma unroll
            for (int r = 0; r < 4; r++) d[mi][ni][r] = 0.f;

    gs_load(Ah, Al, Bh, Bl, bm, bn, K, 0,   sb,       tid);
    gs_load(Ah, Al, Bh, Bl, bm, bn, K, GCK, sb + GST, tid);

    for (int i = 0; i < NCHUNK; i++) {
        const int b = i & 1;
        if (i >= NCHUNK - 2) CP_WAIT(0);
        else                 CP_WAIT(1);
        __syncthreads();

        const uint32_t S = sb + (b ? GST : 0);

#pragma unroll
        for (int ks = 0; ks < 4; ks++) {
            uint32_t ah[4][4], al[4][4], bh[2][4], bl[2][4];
#pragma unroll
            for (int mi = 0; mi < 4; mi++) {
                int row = a_row + mi * 16;
                uint32_t off = (uint32_t)row * 128 +
                    ((uint32_t)(ks * 32 + a_cb) ^ (((uint32_t)row & 7u) << 4));
                LDMATRIX_X4(ah[mi][0], ah[mi][1], ah[mi][2], ah[mi][3], S + off);
                LDMATRIX_X4(al[mi][0], al[mi][1], al[mi][2], al[mi][3], S + 16384 + off);
            }
#pragma unroll
            for (int p = 0; p < 2; p++) {
                int row = b_row + p * 16;
                uint32_t off = (uint32_t)row * 128 +
                    ((uint32_t)(ks * 32 + b_cb) ^ (((uint32_t)row & 7u) << 4));
                LDMATRIX_X4(bh[p][0], bh[p][1], bh[p][2], bh[p][3], S + 32768 + off);
                LDMATRIX_X4(bl[p][0], bl[p][1], bl[p][2], bl[p][3], S + 49152 + off);
            }
#pragma unroll
            for (int mi = 0; mi < 4; mi++) {
#pragma unroll
                for (int p = 0; p < 2; p++) {
                    MMA_F16(d[mi][2 * p],     ah[mi], bh[p][0], bh[p][1]);
                    MMA_F16(d[mi][2 * p],     ah[mi], bl[p][0], bl[p][1]);
                    MMA_F16(d[mi][2 * p],     al[mi], bh[p][0], bh[p][1]);
                    MMA_F16(d[mi][2 * p + 1], ah[mi], bh[p][2], bh[p][3]);
                    MMA_F16(d[mi][2 * p + 1], ah[mi], bl[p][2], bl[p][3]);
                    MMA_F16(d[mi][2 * p + 1], al[mi], bh[p][2], bh[p][3]);
                }
            }
        }
        __syncthreads();

        if (i + 2 < NCHUNK)
            gs_load(Ah, Al, Bh, Bl, bm, bn, K, (i + 2) * GCK,
                    sb + (b ? GST : 0), tid);
    }

    const int gid = lane >> 2, tig = lane & 3;
#pragma unroll
    for (int mi = 0; mi < 4; mi++) {
#pragma unroll
        for (int ni = 0; ni < 4; ni++) {
            int r0 = bm + wm * 64 + mi * 16 + gid;
            int c  = bn + wn * 32 + ni * 8 + tig * 2;
            float bx = bias[c], by = bias[c + 1];
            *(float2*)(Out + (size_t)r0 * N + c) =
                make_float2(d[mi][ni][0] + bx, d[mi][ni][1] + by);
            *(float2*)(Out + (size_t)(r0 + 8) * N + c) =
                make_float2(d[mi][ni][2] + bx, d[mi][ni][3] + by);
        }
    }
}

// ===========================================================================
// RMSNorm + rotary: fp32 in -> fp16 out; optionally also writes lo residual.
// ===========================================================================
__global__ void rmsnorm_rope_split(const float* __restrict__ qf,
                                   __half* __restrict__ oh, __half* __restrict__ ol,
                                   const float* __restrict__ w,
                                   const float* __restrict__ rope,
                                   int write_lo)
{
    int gwarp = (blockIdx.x * blockDim.x + threadIdx.x) >> 5;
    int lane  = threadIdx.x & 31;
    if (gwarp >= SEQ * NH) return;
    int s = gwarp / NH;

    const float* row = qf + (size_t)gwarp * HD;
    float4 v = *(const float4*)(row + lane * 4);
    float ss = v.x * v.x + v.y * v.y + v.z * v.z + v.w * v.w;
#pragma unroll
    for (int m = 16; m; m >>= 1) ss += __shfl_xor_sync(0xffffffffu, ss, m);
    float inv = rsqrtf(ss * (1.0f / HD) + EPSF);

    float4 wv = *(const float4*)(w + lane * 4);
    float x0 = v.x * inv * wv.x;
    float x1 = v.y * inv * wv.y;
    float x2 = v.z * inv * wv.z;
    float x3 = v.w * inv * wv.w;

    const float* rp = rope + (size_t)s * 256 + (size_t)(2 * lane) * 4;
    float4 r0 = *(const float4*)rp;
    float4 r1 = *(const float4*)(rp + 4);
    float o0 = r0.x * x0 + r0.y * x1;
    float o1 = r0.z * x0 + r0.w * x1;
    float o2 = r1.x * x2 + r1.y * x3;
    float o3 = r1.z * x2 + r1.w * x3;

    __half h0 = __float2half_rn(o0), h1 = __float2half_rn(o1);
    __half h2 = __float2half_rn(o2), h3 = __float2half_rn(o3);
    size_t base = (size_t)gwarp * HD + lane * 4;
    uint2 hh;
    hh.x = pack_h2(h0, h1); hh.y = pack_h2(h2, h3);
    *(uint2*)(oh + base) = hh;
    if (write_lo) {
        uint2 ll;
        ll.x = pack_h2(__float2half_rn(o0 - __half2float(h0)),
                       __float2half_rn(o1 - __half2float(h1)));
        ll.y = pack_h2(__float2half_rn(o2 - __half2float(h2)),
                       __float2half_rn(o3 - __half2float(h3)));
        *(uint2*)(ol + base) = ll;
    }
}

// ===========================================================================
// Flash attention: QK^T 2-term (q plain, K split), PV 1-term (P, V plain).
// BR=128, BC=64, 256 threads (8 warps; warp w owns q-rows [w*16, w*16+16)).
// smem: Qh [2ck][128][128B] @0 (32K);
//       stage s @ 32768 + s*49152: Kh 16K, Kl 16K, Vh 16K.
// Total 131072 B.
// ===========================================================================
#define FBR 128
#define FSTB(s) (32768 + (s) * 49152)
#define F_SMEM_BYTES 131072

__device__ __forceinline__ void f_load_kv(
    const __half* __restrict__ Kh, const __half* __restrict__ Kl,
    const __half* __restrict__ Vth,
    int h, int kt, uint32_t st, int tid)
{
    // K tiles: [2ck][64][128B] hi @+0, lo @+16384
#pragma unroll
    for (int j = 0; j < 4; j++) {
        int t = tid + j * 256;
        int r = t >> 4, idx = t & 15;
        int ck = idx >> 3, seg = idx & 7;
        uint32_t dst = st + (uint32_t)(ck * 8192 + r * 128)
                     + (((uint32_t)seg * 16) ^ (((uint32_t)r & 7u) << 4));
        size_t src = (size_t)(kt + r) * CH + h * HD + ck * 64 + seg * 8;
        CP_ASYNC16(dst,         Kh + src);
        CP_ASYNC16(dst + 16384, Kl + src);
    }
    // V tile: [128][128B] hi only @+32768
#pragma unroll
    for (int j = 0; j < 4; j++) {
        int t = tid + j * 256;
        int r = t >> 3, seg = t & 7;
        uint32_t dst = st + 32768 + (uint32_t)(r * 128)
                     + (((uint32_t)seg * 16) ^ (((uint32_t)r & 7u) << 4));
        CP_ASYNC16(dst, Vth + (size_t)(h * HD + r) * SEQ + kt + seg * 8);
    }
}

__global__ void __launch_bounds__(256)
flash_mixed(const __half* __restrict__ Qh,
            const __half* __restrict__ Kh, const __half* __restrict__ Kl,
            const __half* __restrict__ Vth,
            __half* __restrict__ Oh, __half* __restrict__ Ol)
{
    extern __shared__ char smem[];
    const uint32_t sb = smem_u32(smem);

    const int h   = blockIdx.y;
    const int q0  = blockIdx.x * FBR;
    const int tid = threadIdx.x;
    const int wid = tid >> 5, lane = tid & 31;
    const int gid = lane >> 2, tig = lane & 3;
    const float scale = 0.088388347648318447f;   // 1/sqrt(128)

    const int a_row = wid * 16 + (lane & 7) + ((lane >> 3) & 1) * 8;
    const int a_cb  = ((lane >> 4) & 1) * 16;
    const int b_row = (lane & 7) + ((lane >> 4) & 1) * 8;
    const int b_cb  = ((lane >> 3) & 1) * 16;

    // Q load: [2ck][128][128B] (hi only)
#pragma unroll
    for (int j = 0; j < 8; j++) {
        int t = tid + j * 256;
        int r = t >> 4, idx = t & 15;
        int ck = idx >> 3, seg = idx & 7;
        uint32_t dst = sb + (uint32_t)(ck * 16384 + r * 128)
                     + (((uint32_t)seg * 16) ^ (((uint32_t)r & 7u) << 4));
        CP_ASYNC16(dst, Qh + (size_t)(q0 + r) * CH + h * HD + ck * 64 + seg * 8);
    }
    f_load_kv(Kh, Kl, Vth, h, 0, sb + FSTB(0), tid);
    CP_COMMIT();

    float mrow[2] = {-INFINITY, -INFINITY};
    float lrow[2] = {0.f, 0.f};
    float o[16][4];
#pragma unroll
    for (int ni = 0; ni < 16; ni++)
#pragma unroll
        for (int r = 0; r < 4; r++) o[ni][r] = 0.f;

    for (int it = 0; it < SEQ / 64; it++) {
        const int b = it & 1;
        if (it + 1 < SEQ / 64) {
            f_load_kv(Kh, Kl, Vth, h, (it + 1) * 64, sb + FSTB(b ^ 1), tid);
            CP_COMMIT();
            CP_WAIT(1);
        } else {
            CP_WAIT(0);
        }
        __syncthreads();

        const uint32_t SK = sb + FSTB(b);
        const uint32_t SV = SK + 32768;

        // ----- QK^T (2-term): sc[m16][n64] -----
        float sc[8][4];
#pragma unroll
        for (int ni = 0; ni < 8; ni++)
#pragma unroll
            for (int r = 0; r < 4; r++) sc[ni][r] = 0.f;

#pragma unroll
        for (int ks = 0; ks < 8; ks++) {
            const int ck = ks >> 2;
            const uint32_t kb = (uint32_t)((ks & 3) * 32);
            uint32_t qv[4];
            {
                uint32_t off = (uint32_t)(ck * 16384 + a_row * 128)
                             + ((kb + a_cb) ^ (((uint32_t)a_row & 7u) << 4));
                LDMATRIX_X4(qv[0], qv[1], qv[2], qv[3], sb + off);
            }
#pragma unroll
            for (int p = 0; p < 4; p++) {
                int row = p * 16 + b_row;
                uint32_t off = (uint32_t)(ck * 8192 + row * 128)
                             + ((kb + b_cb) ^ (((uint32_t)row & 7u) << 4));
                uint32_t bh[4], bl[4];
                LDMATRIX_X4(bh[0], bh[1], bh[2], bh[3], SK + off);
                LDMATRIX_X4(bl[0], bl[1], bl[2], bl[3], SK + 16384 + off);
                MMA_F16(sc[2 * p],     qv, bh[0], bh[1]);
                MMA_F16(sc[2 * p],     qv, bl[0], bl[1]);
                MMA_F16(sc[2 * p + 1], qv, bh[2], bh[3]);
                MMA_F16(sc[2 * p + 1], qv, bl[2], bl[3]);
            }
        }

        // ----- online softmax (fp32) -----
#pragma unroll
        for (int ni = 0; ni < 8; ni++)
#pragma unroll
            for (int r = 0; r < 4; r++) sc[ni][r] *= scale;

#pragma unroll
        for (int rr = 0; rr < 2; rr++) {
            float rm = -INFINITY;
#pragma unroll
            for (int ni = 0; ni < 8; ni++)
                rm = fmaxf(rm, fmaxf(sc[ni][rr * 2], sc[ni][rr * 2 + 1]));
            rm = fmaxf(rm, __shfl_xor_sync(0xffffffffu, rm, 1));
            rm = fmaxf(rm, __shfl_xor_sync(0xffffffffu, rm, 2));
            float mn = fmaxf(mrow[rr], rm);
            float alpha = __expf(mrow[rr] - mn);
            float rs = 0.f;
#pragma unroll
            for (int ni = 0; ni < 8; ni++) {
                float p0 = __expf(sc[ni][rr * 2]     - mn);
                float p1 = __expf(sc[ni][rr * 2 + 1] - mn);
                sc[ni][rr * 2] = p0; sc[ni][rr * 2 + 1] = p1;
                rs += p0 + p1;
            }
            rs += __shfl_xor_sync(0xffffffffu, rs, 1);
            rs += __shfl_xor_sync(0xffffffffu, rs, 2);
            lrow[rr] = lrow[rr] * alpha + rs;
            mrow[rr] = mn;
#pragma unroll
            for (int ni = 0; ni < 16; ni++) {
                o[ni][rr * 2]     *= alpha;
                o[ni][rr * 2 + 1] *= alpha;
            }
        }

        // ----- P @ V (1-term): P fragments packed plain from sc -----
#pragma unroll
        for (int j = 0; j < 4; j++) {
            uint32_t ph[4];
#pragma unroll
            for (int half = 0; half < 2; half++) {
                const float* s4 = sc[2 * j + half];
                ph[2 * half + 0] = pack_h2(__float2half_rn(s4[0]),
                                           __float2half_rn(s4[1]));
                ph[2 * half + 1] = pack_h2(__float2half_rn(s4[2]),
                                           __float2half_rn(s4[3]));
            }
            const uint32_t kb = (uint32_t)(j * 32);
#pragma unroll
            for (int p = 0; p < 8; p++) {
                int row = p * 16 + b_row;
                uint32_t off = (uint32_t)(row * 128)
                             + ((kb + b_cb) ^ (((uint32_t)row & 7u) << 4));
                uint32_t vh[4];
                LDMATRIX_X4(vh[0], vh[1], vh[2], vh[3], SV + off);
                MMA_F16(o[2 * p],     ph, vh[0], vh[1]);
                MMA_F16(o[2 * p + 1], ph, vh[2], vh[3]);
            }
        }
        __syncthreads();
    }

    // ----- epilogue: normalize, split to fp16 hi/lo (for 3-term Wo GEMM) -----
#pragma unroll
    for (int rr = 0; rr < 2; rr++) {
        float invl = 1.f / lrow[rr];
        int r = q0 + wid * 16 + gid + rr * 8;
#pragma unroll
        for (int ni = 0; ni < 16; ni++) {
            int c = h * HD + ni * 8 + tig * 2;
            float v0 = o[ni][rr * 2] * invl;
            float v1 = o[ni][rr * 2 + 1] * invl;
            __half h0 = __float2half_rn(v0), h1 = __float2half_rn(v1);
            *(uint32_t*)(Oh + (size_t)r * CH + c) = pack_h2(h0, h1);
            *(uint32_t*)(Ol + (size_t)r * CH + c) =
                pack_h2(__float2half_rn(v0 - __half2float(h0)),
                        __float2half_rn(v1 - __half2float(h1)));
        }
    }
}

// ===========================================================================
extern "C" void kernel_launch(void* const* d_in, const int* in_sizes, int n_in,
                              void* d_out, int out_size)
{
    (void)in_sizes; (void)n_in; (void)out_size;
    const float* x    = (const float*)d_in[0];
    const float* rope = (const float*)d_in[1];
    const float* Wq   = (const float*)d_in[2];
    const float* bq   = (const float*)d_in[3];
    const float* Wk   = (const float*)d_in[4];
    const float* bk   = (const float*)d_in[5];
    const float* Wv   = (const float*)d_in[6];
    const float* bv   = (const float*)d_in[7];
    const float* qn   = (const float*)d_in[8];
    const float* kn   = (const float*)d_in[9];
    const float* Wo   = (const float*)d_in[10];
    const float* bo   = (const float*)d_in[11];
    float* out = (float*)d_out;

    __half *xh, *xl, *wqh, *wql, *wkh, *wkl, *wvh, *wvl, *woh, *wol;
    __half *qh, *kh, *kl, *vth, *ah, *al;
    float *qf, *kf, *vf;
    cudaGetSymbolAddress((void**)&xh,  s_xh);  cudaGetSymbolAddress((void**)&xl,  s_xl);
    cudaGetSymbolAddress((void**)&wqh, s_wqh); cudaGetSymbolAddress((void**)&wql, s_wql);
    cudaGetSymbolAddress((void**)&wkh, s_wkh); cudaGetSymbolAddress((void**)&wkl, s_wkl);
    cudaGetSymbolAddress((void**)&wvh, s_wvh); cudaGetSymbolAddress((void**)&wvl, s_wvl);
    cudaGetSymbolAddress((void**)&woh, s_woh); cudaGetSymbolAddress((void**)&wol, s_wol);
    cudaGetSymbolAddress((void**)&qf,  g_qf);  cudaGetSymbolAddress((void**)&kf,  g_kf);
    cudaGetSymbolAddress((void**)&vf,  g_vf);
    cudaGetSymbolAddress((void**)&qh,  s_qh);
    cudaGetSymbolAddress((void**)&kh,  s_kh);  cudaGetSymbolAddress((void**)&kl,  s_kl);
    cudaGetSymbolAddress((void**)&vth, s_vth);
    cudaGetSymbolAddress((void**)&ah,  s_ah);  cudaGetSymbolAddress((void**)&al,  s_al);

    cudaFuncSetAttribute(gemm_split,
        cudaFuncAttributeMaxDynamicSharedMemorySize, GSMEM_BYTES);
    cudaFuncSetAttribute(flash_mixed,
        cudaFuncAttributeMaxDynamicSharedMemorySize, F_SMEM_BYTES);

    // Split inputs into fp16 (hi, lo)
    const int n4x = SEQ * CH / 4, n4w = CH * CH / 4;
    f32_split<<<(n4x + 255) / 256, 256>>>(x,  xh,  xl,  n4x);
    f32_split<<<(n4w + 255) / 256, 256>>>(Wq, wqh, wql, n4w);
    f32_split<<<(n4w + 255) / 256, 256>>>(Wk, wkh, wkl, n4w);
    f32_split<<<(n4w + 255) / 256, 256>>>(Wv, wvh, wvl, n4w);
    f32_split<<<(n4w + 255) / 256, 256>>>(Wo, woh, wol, n4w);

    dim3 gg(CH / GBN, SEQ / GBM);
    gemm_split<<<gg, 256, GSMEM_BYTES>>>(xh, xl, wqh, wql, bq, qf, SEQ, CH, CH);
    gemm_split<<<gg, 256, GSMEM_BYTES>>>(xh, xl, wkh, wkl, bk, kf, SEQ, CH, CH);
    gemm_split<<<gg, 256, GSMEM_BYTES>>>(xh, xl, wvh, wvl, bv, vf, SEQ, CH, CH);

    // q: plain fp16; k: split
    rmsnorm_rope_split<<<SEQ * NH / 8, 256>>>(qf, qh, nullptr, qn, rope, 0);
    rmsnorm_rope_split<<<SEQ * NH / 8, 256>>>(kf, kh, kl, kn, rope, 1);

    // V^T plain fp16
    transpose_plain<<<dim3(CH / 32, SEQ / 32), dim3(32, 8)>>>(vf, vth);

    flash_mixed<<<dim3(SEQ / FBR, NH), 256, F_SMEM_BYTES>>>(
        qh, kh, kl, vth, ah, al);

    gemm_split<<<gg, 256, GSMEM_BYTES>>>(ah, al, woh, wol, bo, out, SEQ, CH, CH);
}